// round 1
// baseline (speedup 1.0000x reference)
#include <cuda_runtime.h>
#include <math.h>

// Problem dims (fixed by setup_inputs)
#define B_  4
#define N_  1024
#define C_  1024
#define H_  16
#define DH  64
#define BH  (B_*H_)          // 64
#define ROWS (BH*N_)         // 65536 entmax rows

// ---------------- scratch (static device globals; no allocation) ------------
__device__ float g_q[(size_t)B_*H_*N_*DH];    // [B,H,N,Dh]
__device__ float g_k[(size_t)B_*H_*N_*DH];
__device__ float g_v[(size_t)B_*H_*N_*DH];
__device__ float g_ctx[(size_t)B_*N_*C_];     // [B,N,C]

// ---------------- generic tiled SGEMM: C = A[MxK] @ W[KxN] + bias -----------
// head_mode=1: write into [B,H,N,Dh] layout (row = b*N+n, col = h*Dh+d)
__global__ void sgemm_bias_kernel(const float* __restrict__ A,
                                  const float* __restrict__ W,
                                  const float* __restrict__ bias,
                                  float* __restrict__ C,
                                  int M, int N, int K, int head_mode)
{
    const int BM = 64, BN = 64, BK = 16;
    __shared__ float As[BK][BM + 1];
    __shared__ float Bs[BK][BN + 1];

    int tid = threadIdx.x;
    int tx = tid & 15, ty = tid >> 4;
    int rowBase = blockIdx.y * BM;
    int colBase = blockIdx.x * BN;

    float acc[4][4] = {};

    for (int k0 = 0; k0 < K; k0 += BK) {
        #pragma unroll
        for (int i = tid; i < BM * BK; i += 256) {
            int r = i >> 4, c = i & 15;
            As[c][r] = A[(size_t)(rowBase + r) * K + k0 + c];
        }
        #pragma unroll
        for (int i = tid; i < BK * BN; i += 256) {
            int r = i >> 6, c = i & 63;
            Bs[r][c] = W[(size_t)(k0 + r) * N + colBase + c];
        }
        __syncthreads();

        #pragma unroll
        for (int kk = 0; kk < BK; kk++) {
            float a[4], b[4];
            #pragma unroll
            for (int i = 0; i < 4; i++) a[i] = As[kk][ty * 4 + i];
            #pragma unroll
            for (int j = 0; j < 4; j++) b[j] = Bs[kk][tx * 4 + j];
            #pragma unroll
            for (int i = 0; i < 4; i++)
                #pragma unroll
                for (int j = 0; j < 4; j++)
                    acc[i][j] = fmaf(a[i], b[j], acc[i][j]);
        }
        __syncthreads();
    }

    #pragma unroll
    for (int i = 0; i < 4; i++) {
        int row = rowBase + ty * 4 + i;
        #pragma unroll
        for (int j = 0; j < 4; j++) {
            int col = colBase + tx * 4 + j;
            float v = acc[i][j] + bias[col];
            if (head_mode) {
                int bb = row >> 10, n = row & 1023;
                int h  = col >> 6,  d = col & 63;
                C[(((size_t)bb * H_ + h) * N_ + n) * DH + d] = v;
            } else {
                C[(size_t)row * N + col] = v;
            }
        }
    }
}

// ---------------- scores: per (b,h)  S = Q @ K^T * 0.125 --------------------
__global__ void scores_kernel(const float* __restrict__ Q,
                              const float* __restrict__ Km,
                              float* __restrict__ S)
{
    const int BM = 64, BN = 64, BK = 16;
    __shared__ float Qs[BK][BM + 1];   // [k][m]
    __shared__ float Ks[BN][BK + 1];   // [n][k]

    int z = blockIdx.z;                            // b*H + h
    const float* Qb = Q  + (size_t)z * N_ * DH;
    const float* Kb = Km + (size_t)z * N_ * DH;

    int tid = threadIdx.x;
    int tx = tid & 15, ty = tid >> 4;
    int rowBase = blockIdx.y * BM;
    int colBase = blockIdx.x * BN;

    float acc[4][4] = {};

    for (int k0 = 0; k0 < DH; k0 += BK) {
        #pragma unroll
        for (int i = tid; i < BM * BK; i += 256) {
            int r = i >> 4, c = i & 15;
            Qs[c][r] = Qb[(rowBase + r) * DH + k0 + c];
        }
        #pragma unroll
        for (int i = tid; i < BN * BK; i += 256) {
            int n = i >> 4, r = i & 15;
            Ks[n][r] = Kb[(colBase + n) * DH + k0 + r];
        }
        __syncthreads();

        #pragma unroll
        for (int kk = 0; kk < BK; kk++) {
            float a[4], b[4];
            #pragma unroll
            for (int i = 0; i < 4; i++) a[i] = Qs[kk][ty * 4 + i];
            #pragma unroll
            for (int j = 0; j < 4; j++) b[j] = Ks[tx * 4 + j][kk];
            #pragma unroll
            for (int i = 0; i < 4; i++)
                #pragma unroll
                for (int j = 0; j < 4; j++)
                    acc[i][j] = fmaf(a[i], b[j], acc[i][j]);
        }
        __syncthreads();
    }

    float* Sb = S + (size_t)z * N_ * N_;
    #pragma unroll
    for (int i = 0; i < 4; i++) {
        int row = rowBase + ty * 4 + i;
        #pragma unroll
        for (int j = 0; j < 4; j++) {
            int col = colBase + tx * 4 + j;
            Sb[(size_t)row * N_ + col] = acc[i][j] * 0.125f;
        }
    }
}

// ---------------- entmax bisect (alpha=1.5, 50 iters), in place -------------
// One warp per row of 1024; the row lives in 32 registers per lane.
__global__ void entmax_kernel(float* __restrict__ attn)
{
    int warp = threadIdx.x >> 5;
    int lane = threadIdx.x & 31;
    size_t row = (size_t)blockIdx.x * 8 + warp;    // ROWS rows total
    float* S = attn + row * N_;

    // Xa = X * (alpha-1) = X * 0.5 ; track max
    float xa[32];
    float mx = -INFINITY;
    #pragma unroll
    for (int i = 0; i < 32; i++) {
        float v = S[i * 32 + lane] * 0.5f;
        xa[i] = v;
        mx = fmaxf(mx, v);
    }
    #pragma unroll
    for (int o = 16; o; o >>= 1)
        mx = fmaxf(mx, __shfl_xor_sync(0xFFFFFFFFu, mx, o));

    float tau_lo = mx - 1.0f;
    float tau_hi = mx - 0.03125f;      // (1/1024)^0.5
    float dm = tau_hi - tau_lo;

    float f_lo = 0.0f;
    #pragma unroll
    for (int i = 0; i < 32; i++) {
        float t = fmaxf(xa[i] - tau_lo, 0.0f);
        f_lo += t * t;
    }
    #pragma unroll
    for (int o = 16; o; o >>= 1)
        f_lo += __shfl_xor_sync(0xFFFFFFFFu, f_lo, o);
    f_lo -= 1.0f;

    float tau_m = tau_lo;
    for (int it = 0; it < 50; it++) {
        dm *= 0.5f;
        tau_m = tau_lo + dm;
        float f = 0.0f;
        #pragma unroll
        for (int i = 0; i < 32; i++) {
            float t = fmaxf(xa[i] - tau_m, 0.0f);
            f += t * t;
        }
        #pragma unroll
        for (int o = 16; o; o >>= 1)
            f += __shfl_xor_sync(0xFFFFFFFFu, f, o);
        f -= 1.0f;
        if (f * f_lo >= 0.0f) tau_lo = tau_m;
    }

    // final p from last tau_m, normalized to sum 1
    float p[32];
    float s = 0.0f;
    #pragma unroll
    for (int i = 0; i < 32; i++) {
        float t = fmaxf(xa[i] - tau_m, 0.0f);
        p[i] = t * t;
        s += p[i];
    }
    #pragma unroll
    for (int o = 16; o; o >>= 1)
        s += __shfl_xor_sync(0xFFFFFFFFu, s, o);
    float inv = 1.0f / s;

    #pragma unroll
    for (int i = 0; i < 32; i++)
        S[i * 32 + lane] = p[i] * inv;
}

// ---------------- ctx = attn @ V per (b,h), written to [B,N,C] --------------
__global__ void attnv_kernel(const float* __restrict__ Attn,
                             const float* __restrict__ V,
                             float* __restrict__ ctx)
{
    const int BM = 64, BN = 64, BK = 16;
    __shared__ float As[BK][BM + 1];   // [k][m]
    __shared__ float Vs[BK][BN + 1];   // [k][d]

    int z = blockIdx.z;
    int bb = z >> 4, h = z & 15;
    const float* Ab = Attn + (size_t)z * N_ * N_;
    const float* Vb = V    + (size_t)z * N_ * DH;

    int tid = threadIdx.x;
    int tx = tid & 15, ty = tid >> 4;
    int rowBase = blockIdx.y * BM;

    float acc[4][4] = {};

    for (int k0 = 0; k0 < N_; k0 += BK) {
        #pragma unroll
        for (int i = tid; i < BM * BK; i += 256) {
            int r = i >> 4, c = i & 15;
            As[c][r] = Ab[(size_t)(rowBase + r) * N_ + k0 + c];
        }
        #pragma unroll
        for (int i = tid; i < BK * BN; i += 256) {
            int r = i >> 6, c = i & 63;
            Vs[r][c] = Vb[(k0 + r) * DH + c];
        }
        __syncthreads();

        #pragma unroll
        for (int kk = 0; kk < BK; kk++) {
            float a[4], b[4];
            #pragma unroll
            for (int i = 0; i < 4; i++) a[i] = As[kk][ty * 4 + i];
            #pragma unroll
            for (int j = 0; j < 4; j++) b[j] = Vs[kk][tx * 4 + j];
            #pragma unroll
            for (int i = 0; i < 4; i++)
                #pragma unroll
                for (int j = 0; j < 4; j++)
                    acc[i][j] = fmaf(a[i], b[j], acc[i][j]);
        }
        __syncthreads();
    }

    #pragma unroll
    for (int i = 0; i < 4; i++) {
        int n = rowBase + ty * 4 + i;
        #pragma unroll
        for (int j = 0; j < 4; j++) {
            int d = tx * 4 + j;
            ctx[((size_t)bb * N_ + n) * C_ + h * DH + d] = acc[i][j];
        }
    }
}

// ---------------- launcher ---------------------------------------------------
extern "C" void kernel_launch(void* const* d_in, const int* in_sizes, int n_in,
                              void* d_out, int out_size)
{
    const float* x  = (const float*)d_in[0];
    const float* Wq = (const float*)d_in[1];
    const float* bq = (const float*)d_in[2];
    const float* Wk = (const float*)d_in[3];
    const float* bk = (const float*)d_in[4];
    const float* Wv = (const float*)d_in[5];
    const float* bv = (const float*)d_in[6];
    const float* Wo = (const float*)d_in[7];
    const float* bo = (const float*)d_in[8];

    float* out = (float*)d_out;
    const size_t attn_elems = (size_t)B_ * H_ * N_ * N_;   // 67108864
    // outputs are (proj_out [B,N,C], attn [B,H,N,N]) flattened in order;
    // place attn at the tail so this stays correct for out_size layout.
    float* attn = out + ((size_t)out_size - attn_elems);

    float *q, *k, *v, *ctx;
    cudaGetSymbolAddress((void**)&q,   g_q);
    cudaGetSymbolAddress((void**)&k,   g_k);
    cudaGetSymbolAddress((void**)&v,   g_v);
    cudaGetSymbolAddress((void**)&ctx, g_ctx);

    dim3 blk(256);
    const int M = B_ * N_;   // 4096

    // QKV projections into [B,H,N,Dh]
    sgemm_bias_kernel<<<dim3(16, 64), blk>>>(x, Wq, bq, q, M, C_, C_, 1);
    sgemm_bias_kernel<<<dim3(16, 64), blk>>>(x, Wk, bk, k, M, C_, C_, 1);
    sgemm_bias_kernel<<<dim3(16, 64), blk>>>(x, Wv, bv, v, M, C_, C_, 1);

    // scores straight into the attn output region
    scores_kernel<<<dim3(16, 16, BH), blk>>>(q, k, attn);

    // entmax bisection in place (one warp per row)
    entmax_kernel<<<dim3(ROWS / 8), blk>>>(attn);

    // ctx = attn @ V  -> [B,N,C]
    attnv_kernel<<<dim3(1, 16, BH), blk>>>(attn, v, ctx);

    // final projection -> first B*N*C elements of d_out
    sgemm_bias_kernel<<<dim3(16, 64), blk>>>(ctx, Wo, bo, out, M, C_, C_, 0);
}

// round 2
// speedup vs baseline: 1.6205x; 1.6205x over previous
#include <cuda_runtime.h>
#include <math.h>

#define B_  4
#define N_  1024
#define C_  1024
#define H_  16
#define DH  64
#define BH  (B_*H_)
#define ROWS (BH*N_)

// ---------------- scratch -----------------------------------------------------
__device__ float g_q[(size_t)B_*H_*N_*DH];
__device__ float g_k[(size_t)B_*H_*N_*DH];
__device__ float g_v[(size_t)B_*H_*N_*DH];
__device__ float g_ctx[(size_t)B_*N_*C_];

// ============ 128x128x16 SGEMM core: C = A[4096x1024] @ W[1024x1024] + b ======
// head_mode=1 -> scatter into [B,H,N,Dh]
__device__ __forceinline__ void gemm128_body(const float* __restrict__ A,
                                             const float* __restrict__ W,
                                             const float* __restrict__ bias,
                                             float* __restrict__ C,
                                             int head_mode)
{
    __shared__ float As[16][128];
    __shared__ float Bs[16][128];

    const int K = C_, Nn = C_;
    int tid = threadIdx.x;
    int tx = tid & 15, ty = tid >> 4;
    int row0 = blockIdx.y * 128;
    int col0 = blockIdx.x * 128;

    float acc[8][8] = {};

    for (int k0 = 0; k0 < K; k0 += 16) {
        #pragma unroll
        for (int i = 0; i < 2; i++) {
            int idx = tid + i * 256;
            int r = idx >> 2, c4 = (idx & 3) * 4;
            float4 a = *(const float4*)&A[(size_t)(row0 + r) * K + k0 + c4];
            As[c4 + 0][r] = a.x; As[c4 + 1][r] = a.y;
            As[c4 + 2][r] = a.z; As[c4 + 3][r] = a.w;
        }
        #pragma unroll
        for (int i = 0; i < 2; i++) {
            int idx = tid + i * 256;
            int r = idx >> 5, c4 = (idx & 31) * 4;
            *(float4*)&Bs[r][c4] = *(const float4*)&W[(size_t)(k0 + r) * Nn + col0 + c4];
        }
        __syncthreads();

        #pragma unroll
        for (int kk = 0; kk < 16; kk++) {
            float a[8], b[8];
            *(float4*)(a)     = *(float4*)&As[kk][ty * 4];
            *(float4*)(a + 4) = *(float4*)&As[kk][64 + ty * 4];
            *(float4*)(b)     = *(float4*)&Bs[kk][tx * 4];
            *(float4*)(b + 4) = *(float4*)&Bs[kk][64 + tx * 4];
            #pragma unroll
            for (int i = 0; i < 8; i++)
                #pragma unroll
                for (int j = 0; j < 8; j++)
                    acc[i][j] = fmaf(a[i], b[j], acc[i][j]);
        }
        __syncthreads();
    }

    #pragma unroll
    for (int i = 0; i < 8; i++) {
        int row = row0 + ((i < 4) ? (ty * 4 + i) : (64 + ty * 4 + i - 4));
        #pragma unroll
        for (int jh = 0; jh < 2; jh++) {
            int col = col0 + jh * 64 + tx * 4;
            float4 o;
            o.x = acc[i][jh * 4 + 0] + bias[col + 0];
            o.y = acc[i][jh * 4 + 1] + bias[col + 1];
            o.z = acc[i][jh * 4 + 2] + bias[col + 2];
            o.w = acc[i][jh * 4 + 3] + bias[col + 3];
            if (head_mode) {
                int bb = row >> 10, n = row & 1023;
                int h = col >> 6, d = col & 63;
                *(float4*)&C[(((size_t)bb * H_ + h) * N_ + n) * DH + d] = o;
            } else {
                *(float4*)&C[(size_t)row * Nn + col] = o;
            }
        }
    }
}

__global__ void __launch_bounds__(256)
qkv_kernel(const float* __restrict__ x,
           const float* __restrict__ Wq, const float* __restrict__ bq,
           const float* __restrict__ Wk, const float* __restrict__ bk,
           const float* __restrict__ Wv, const float* __restrict__ bv,
           float* __restrict__ q, float* __restrict__ k, float* __restrict__ v)
{
    int z = blockIdx.z;
    if (z == 0)      gemm128_body(x, Wq, bq, q, 1);
    else if (z == 1) gemm128_body(x, Wk, bk, k, 1);
    else             gemm128_body(x, Wv, bv, v, 1);
}

__global__ void __launch_bounds__(256)
proj_kernel(const float* __restrict__ A, const float* __restrict__ W,
            const float* __restrict__ bias, float* __restrict__ C)
{
    gemm128_body(A, W, bias, C, 0);
}

// ============ scores: per (b,h), S = Q @ K^T * 0.125, 128x128 tiles ===========
__global__ void __launch_bounds__(256)
scores_kernel(const float* __restrict__ Q, const float* __restrict__ Km,
              float* __restrict__ S)
{
    __shared__ float Qs[32][128];
    __shared__ float Ks[32][128];

    int z = blockIdx.z;
    const float* Qb = Q  + (size_t)z * N_ * DH;
    const float* Kb = Km + (size_t)z * N_ * DH;

    int tid = threadIdx.x;
    int tx = tid & 15, ty = tid >> 4;
    int row0 = blockIdx.y * 128;
    int col0 = blockIdx.x * 128;

    float acc[8][8] = {};

    #pragma unroll
    for (int c0 = 0; c0 < DH; c0 += 32) {
        #pragma unroll
        for (int i = 0; i < 4; i++) {
            int idx = tid + i * 256;
            int r = idx >> 3, k4 = (idx & 7) * 4;
            float4 a = *(const float4*)&Qb[(size_t)(row0 + r) * DH + c0 + k4];
            Qs[k4 + 0][r] = a.x; Qs[k4 + 1][r] = a.y;
            Qs[k4 + 2][r] = a.z; Qs[k4 + 3][r] = a.w;
            float4 b = *(const float4*)&Kb[(size_t)(col0 + r) * DH + c0 + k4];
            Ks[k4 + 0][r] = b.x; Ks[k4 + 1][r] = b.y;
            Ks[k4 + 2][r] = b.z; Ks[k4 + 3][r] = b.w;
        }
        __syncthreads();

        #pragma unroll
        for (int kk = 0; kk < 32; kk++) {
            float a[8], b[8];
            *(float4*)(a)     = *(float4*)&Qs[kk][ty * 4];
            *(float4*)(a + 4) = *(float4*)&Qs[kk][64 + ty * 4];
            *(float4*)(b)     = *(float4*)&Ks[kk][tx * 4];
            *(float4*)(b + 4) = *(float4*)&Ks[kk][64 + tx * 4];
            #pragma unroll
            for (int i = 0; i < 8; i++)
                #pragma unroll
                for (int j = 0; j < 8; j++)
                    acc[i][j] = fmaf(a[i], b[j], acc[i][j]);
        }
        __syncthreads();
    }

    float* Sb = S + (size_t)z * N_ * N_;
    #pragma unroll
    for (int i = 0; i < 8; i++) {
        int row = row0 + ((i < 4) ? (ty * 4 + i) : (64 + ty * 4 + i - 4));
        #pragma unroll
        for (int jh = 0; jh < 2; jh++) {
            int col = col0 + jh * 64 + tx * 4;
            float4 o;
            o.x = acc[i][jh * 4 + 0] * 0.125f;
            o.y = acc[i][jh * 4 + 1] * 0.125f;
            o.z = acc[i][jh * 4 + 2] * 0.125f;
            o.w = acc[i][jh * 4 + 3] * 0.125f;
            *(float4*)&Sb[(size_t)row * N_ + col] = o;
        }
    }
}

// ============ entmax bisect (alpha=1.5, 50 iters), in place ===================
__global__ void entmax_kernel(float* __restrict__ attn)
{
    int warp = threadIdx.x >> 5;
    int lane = threadIdx.x & 31;
    size_t row = (size_t)blockIdx.x * 8 + warp;
    float* S = attn + row * N_;

    float xa[32];
    float mx = -INFINITY;
    #pragma unroll
    for (int i = 0; i < 32; i++) {
        float v = S[i * 32 + lane] * 0.5f;
        xa[i] = v;
        mx = fmaxf(mx, v);
    }
    #pragma unroll
    for (int o = 16; o; o >>= 1)
        mx = fmaxf(mx, __shfl_xor_sync(0xFFFFFFFFu, mx, o));

    float tau_lo = mx - 1.0f;
    float dm = 1.0f - 0.03125f;   // tau_hi - tau_lo

    float f_lo = 0.0f;
    #pragma unroll
    for (int i = 0; i < 32; i++) {
        float t = fmaxf(xa[i] - tau_lo, 0.0f);
        f_lo = fmaf(t, t, f_lo);
    }
    #pragma unroll
    for (int o = 16; o; o >>= 1)
        f_lo += __shfl_xor_sync(0xFFFFFFFFu, f_lo, o);
    f_lo -= 1.0f;

    float tau_m = tau_lo;
    for (int it = 0; it < 50; it++) {
        dm *= 0.5f;
        tau_m = tau_lo + dm;
        float f = 0.0f;
        #pragma unroll
        for (int i = 0; i < 32; i++) {
            float t = fmaxf(xa[i] - tau_m, 0.0f);
            f = fmaf(t, t, f);
        }
        #pragma unroll
        for (int o = 16; o; o >>= 1)
            f += __shfl_xor_sync(0xFFFFFFFFu, f, o);
        f -= 1.0f;
        if (f * f_lo >= 0.0f) tau_lo = tau_m;
    }

    float p[32];
    float s = 0.0f;
    #pragma unroll
    for (int i = 0; i < 32; i++) {
        float t = fmaxf(xa[i] - tau_m, 0.0f);
        p[i] = t * t;
        s += p[i];
    }
    #pragma unroll
    for (int o = 16; o; o >>= 1)
        s += __shfl_xor_sync(0xFFFFFFFFu, s, o);
    float inv = 1.0f / s;

    #pragma unroll
    for (int i = 0; i < 32; i++)
        S[i * 32 + lane] = p[i] * inv;
}

// ============ ctx = attn @ V per (b,h): 128x64 tiles, BK=16 ===================
__global__ void __launch_bounds__(256)
attnv_kernel(const float* __restrict__ Attn, const float* __restrict__ V,
             float* __restrict__ ctx)
{
    __shared__ float As[16][128];
    __shared__ float Vs[16][64];

    int z = blockIdx.z;
    int bb = z >> 4, h = z & 15;
    const float* Ab = Attn + (size_t)z * N_ * N_;
    const float* Vb = V    + (size_t)z * N_ * DH;

    int tid = threadIdx.x;
    int tx = tid & 15, ty = tid >> 4;
    int row0 = blockIdx.y * 128;

    float acc[8][4] = {};

    for (int k0 = 0; k0 < N_; k0 += 16) {
        #pragma unroll
        for (int i = 0; i < 2; i++) {
            int idx = tid + i * 256;
            int r = idx >> 2, c4 = (idx & 3) * 4;
            float4 a = *(const float4*)&Ab[(size_t)(row0 + r) * N_ + k0 + c4];
            As[c4 + 0][r] = a.x; As[c4 + 1][r] = a.y;
            As[c4 + 2][r] = a.z; As[c4 + 3][r] = a.w;
        }
        {
            int r = tid >> 4, c4 = (tid & 15) * 4;
            *(float4*)&Vs[r][c4] = *(const float4*)&Vb[(size_t)(k0 + r) * DH + c4];
        }
        __syncthreads();

        #pragma unroll
        for (int kk = 0; kk < 16; kk++) {
            float a[8], b[4];
            *(float4*)(a)     = *(float4*)&As[kk][ty * 4];
            *(float4*)(a + 4) = *(float4*)&As[kk][64 + ty * 4];
            *(float4*)(b)     = *(float4*)&Vs[kk][tx * 4];
            #pragma unroll
            for (int i = 0; i < 8; i++)
                #pragma unroll
                for (int j = 0; j < 4; j++)
                    acc[i][j] = fmaf(a[i], b[j], acc[i][j]);
        }
        __syncthreads();
    }

    #pragma unroll
    for (int i = 0; i < 8; i++) {
        int n = row0 + ((i < 4) ? (ty * 4 + i) : (64 + ty * 4 + i - 4));
        int d = tx * 4;
        float4 o;
        o.x = acc[i][0]; o.y = acc[i][1]; o.z = acc[i][2]; o.w = acc[i][3];
        *(float4*)&ctx[((size_t)bb * N_ + n) * C_ + h * DH + d] = o;
    }
}

// ============ launcher ========================================================
extern "C" void kernel_launch(void* const* d_in, const int* in_sizes, int n_in,
                              void* d_out, int out_size)
{
    const float* x  = (const float*)d_in[0];
    const float* Wq = (const float*)d_in[1];
    const float* bq = (const float*)d_in[2];
    const float* Wk = (const float*)d_in[3];
    const float* bk = (const float*)d_in[4];
    const float* Wv = (const float*)d_in[5];
    const float* bv = (const float*)d_in[6];
    const float* Wo = (const float*)d_in[7];
    const float* bo = (const float*)d_in[8];

    float* out = (float*)d_out;
    const size_t attn_elems = (size_t)B_ * H_ * N_ * N_;
    float* attn = out + ((size_t)out_size - attn_elems);

    float *q, *k, *v, *ctx;
    cudaGetSymbolAddress((void**)&q,   g_q);
    cudaGetSymbolAddress((void**)&k,   g_k);
    cudaGetSymbolAddress((void**)&v,   g_v);
    cudaGetSymbolAddress((void**)&ctx, g_ctx);

    dim3 blk(256);

    qkv_kernel<<<dim3(8, 32, 3), blk>>>(x, Wq, bq, Wk, bk, Wv, bv, q, k, v);
    scores_kernel<<<dim3(8, 8, BH), blk>>>(q, k, attn);
    entmax_kernel<<<dim3(ROWS / 8), blk>>>(attn);
    attnv_kernel<<<dim3(1, 8, BH), blk>>>(attn, v, ctx);
    proj_kernel<<<dim3(8, 32), blk>>>(ctx, Wo, bo, out);
}

// round 3
// speedup vs baseline: 2.0916x; 1.2907x over previous
#include <cuda_runtime.h>
#include <math.h>
#include <stdint.h>

#define B_  4
#define N_  1024
#define C_  1024
#define H_  16
#define DH  64
#define BH  (B_*H_)
#define ROWS (BH*N_)

// ---------------- scratch -----------------------------------------------------
__device__ float g_q[(size_t)B_*H_*N_*DH];
__device__ float g_k[(size_t)B_*H_*N_*DH];
__device__ float g_v[(size_t)B_*H_*N_*DH];
__device__ float g_ctx[(size_t)B_*N_*C_];

// ---------------- tf32 helpers ------------------------------------------------
__device__ __forceinline__ uint32_t f2tf(float x) {
    uint32_t r;
    asm("cvt.rna.tf32.f32 %0, %1;" : "=r"(r) : "f"(x));
    return r;
}
// x = hi + lo, hi exactly representable in tf32; lo passed as raw f32 bits
// (HMMA truncates it to tf32 -> residual error ~2^-22 relative).
__device__ __forceinline__ void split_tf(float x, uint32_t& hi, uint32_t& lo) {
    hi = f2tf(x);
    lo = __float_as_uint(x - __uint_as_float(hi));
}

__device__ __forceinline__ void mma8(float c[4],
                                     uint32_t a0, uint32_t a1, uint32_t a2, uint32_t a3,
                                     uint32_t b0, uint32_t b1) {
    asm("mma.sync.aligned.m16n8k8.row.col.f32.tf32.tf32.f32 "
        "{%0,%1,%2,%3},{%4,%5,%6,%7},{%8,%9},{%0,%1,%2,%3};"
        : "+f"(c[0]), "+f"(c[1]), "+f"(c[2]), "+f"(c[3])
        : "r"(a0), "r"(a1), "r"(a2), "r"(a3), "r"(b0), "r"(b1));
}

// ============ 128x128 CTA, 64x32 warp tiles, 3xTF32: C = A@W (+bias) ==========
// A: [4096 x 1024] row-major, W: [1024 x 1024] row-major.
// head_mode=1 -> scatter into [B,H,N,Dh]
__device__ __forceinline__ void gemm_tc_body(const float* __restrict__ A,
                                             const float* __restrict__ W,
                                             const float* __restrict__ bias,
                                             float* __restrict__ C,
                                             int head_mode)
{
    __shared__ float As[32][132];   // [k][m]
    __shared__ float Bs[32][132];   // [k][n]

    const int K = C_, Nn = C_;
    int tid = threadIdx.x;
    int lane = tid & 31, wid = tid >> 5;
    int g = lane >> 2, q = lane & 3;
    int wm = wid >> 2, wn = wid & 3;          // warps 2x4
    int row0 = blockIdx.y * 128;
    int col0 = blockIdx.x * 128;

    float acc[4][4][4] = {};

    for (int k0 = 0; k0 < K; k0 += 32) {
        // A tile 128x32, transpose to [k][m]
        #pragma unroll
        for (int i = 0; i < 4; i++) {
            int idx = tid + i * 256;
            int r = idx >> 3, c4 = (idx & 7) * 4;
            float4 a = *(const float4*)&A[(size_t)(row0 + r) * K + k0 + c4];
            As[c4 + 0][r] = a.x; As[c4 + 1][r] = a.y;
            As[c4 + 2][r] = a.z; As[c4 + 3][r] = a.w;
        }
        // B tile 32x128, direct [k][n]
        #pragma unroll
        for (int i = 0; i < 4; i++) {
            int idx = tid + i * 256;
            int r = idx >> 5, c4 = (idx & 31) * 4;
            *(float4*)&Bs[r][c4] = *(const float4*)&W[(size_t)(k0 + r) * Nn + col0 + c4];
        }
        __syncthreads();

        #pragma unroll
        for (int ks = 0; ks < 4; ks++) {
            int kb = ks * 8;
            uint32_t bh[4][2], bl[4][2];
            #pragma unroll
            for (int fn = 0; fn < 4; fn++) {
                int col = wn * 32 + fn * 8 + g;
                split_tf(Bs[kb + q][col],     bh[fn][0], bl[fn][0]);
                split_tf(Bs[kb + q + 4][col], bh[fn][1], bl[fn][1]);
            }
            #pragma unroll
            for (int fm = 0; fm < 4; fm++) {
                int m = wm * 64 + fm * 16 + g;
                uint32_t ah[4], al[4];
                split_tf(As[kb + q][m],         ah[0], al[0]);
                split_tf(As[kb + q][m + 8],     ah[1], al[1]);
                split_tf(As[kb + q + 4][m],     ah[2], al[2]);
                split_tf(As[kb + q + 4][m + 8], ah[3], al[3]);
                #pragma unroll
                for (int fn = 0; fn < 4; fn++) {
                    mma8(acc[fm][fn], ah[0], ah[1], ah[2], ah[3], bh[fn][0], bh[fn][1]);
                    mma8(acc[fm][fn], ah[0], ah[1], ah[2], ah[3], bl[fn][0], bl[fn][1]);
                    mma8(acc[fm][fn], al[0], al[1], al[2], al[3], bh[fn][0], bh[fn][1]);
                }
            }
        }
        __syncthreads();
    }

    #pragma unroll
    for (int fm = 0; fm < 4; fm++) {
        int rowA = row0 + wm * 64 + fm * 16 + g;
        #pragma unroll
        for (int fn = 0; fn < 4; fn++) {
            int col = col0 + wn * 32 + fn * 8 + 2 * q;
            float2 p0, p1;
            p0.x = acc[fm][fn][0] + bias[col];
            p0.y = acc[fm][fn][1] + bias[col + 1];
            p1.x = acc[fm][fn][2] + bias[col];
            p1.y = acc[fm][fn][3] + bias[col + 1];
            if (head_mode) {
                int h = col >> 6, d = col & 63;
                int bb0 = rowA >> 10, n0 = rowA & 1023;
                int bb1 = (rowA + 8) >> 10, n1 = (rowA + 8) & 1023;
                *(float2*)&C[(((size_t)bb0 * H_ + h) * N_ + n0) * DH + d] = p0;
                *(float2*)&C[(((size_t)bb1 * H_ + h) * N_ + n1) * DH + d] = p1;
            } else {
                *(float2*)&C[(size_t)rowA * Nn + col] = p0;
                *(float2*)&C[(size_t)(rowA + 8) * Nn + col] = p1;
            }
        }
    }
}

__global__ void __launch_bounds__(256, 2)
qkv_kernel(const float* __restrict__ x,
           const float* __restrict__ Wq, const float* __restrict__ bq,
           const float* __restrict__ Wk, const float* __restrict__ bk,
           const float* __restrict__ Wv, const float* __restrict__ bv,
           float* __restrict__ q, float* __restrict__ k, float* __restrict__ v)
{
    int z = blockIdx.z;
    if (z == 0)      gemm_tc_body(x, Wq, bq, q, 1);
    else if (z == 1) gemm_tc_body(x, Wk, bk, k, 1);
    else             gemm_tc_body(x, Wv, bv, v, 1);
}

__global__ void __launch_bounds__(256, 2)
proj_kernel(const float* __restrict__ A, const float* __restrict__ W,
            const float* __restrict__ bias, float* __restrict__ C)
{
    gemm_tc_body(A, W, bias, C, 0);
}

// ============ scores: per (b,h), S = Q @ K^T * 0.125 (3xTF32) =================
__global__ void __launch_bounds__(256, 2)
scores_kernel(const float* __restrict__ Q, const float* __restrict__ Km,
              float* __restrict__ S)
{
    __shared__ float Qs[32][132];   // [k][m]
    __shared__ float Ks[32][132];   // [k][n]  (K transposed: Ks[k][n] = K[n][k])

    int z = blockIdx.z;
    const float* Qb = Q  + (size_t)z * N_ * DH;
    const float* Kb = Km + (size_t)z * N_ * DH;

    int tid = threadIdx.x;
    int lane = tid & 31, wid = tid >> 5;
    int g = lane >> 2, q = lane & 3;
    int wm = wid >> 2, wn = wid & 3;
    int row0 = blockIdx.y * 128;
    int col0 = blockIdx.x * 128;

    float acc[4][4][4] = {};

    #pragma unroll
    for (int k0 = 0; k0 < DH; k0 += 32) {
        #pragma unroll
        for (int i = 0; i < 4; i++) {
            int idx = tid + i * 256;
            int r = idx >> 3, c4 = (idx & 7) * 4;
            float4 a = *(const float4*)&Qb[(size_t)(row0 + r) * DH + k0 + c4];
            Qs[c4 + 0][r] = a.x; Qs[c4 + 1][r] = a.y;
            Qs[c4 + 2][r] = a.z; Qs[c4 + 3][r] = a.w;
            float4 b = *(const float4*)&Kb[(size_t)(col0 + r) * DH + k0 + c4];
            Ks[c4 + 0][r] = b.x; Ks[c4 + 1][r] = b.y;
            Ks[c4 + 2][r] = b.z; Ks[c4 + 3][r] = b.w;
        }
        __syncthreads();

        #pragma unroll
        for (int ks = 0; ks < 4; ks++) {
            int kb = ks * 8;
            uint32_t bh[4][2], bl[4][2];
            #pragma unroll
            for (int fn = 0; fn < 4; fn++) {
                int col = wn * 32 + fn * 8 + g;
                split_tf(Ks[kb + q][col],     bh[fn][0], bl[fn][0]);
                split_tf(Ks[kb + q + 4][col], bh[fn][1], bl[fn][1]);
            }
            #pragma unroll
            for (int fm = 0; fm < 4; fm++) {
                int m = wm * 64 + fm * 16 + g;
                uint32_t ah[4], al[4];
                split_tf(Qs[kb + q][m],         ah[0], al[0]);
                split_tf(Qs[kb + q][m + 8],     ah[1], al[1]);
                split_tf(Qs[kb + q + 4][m],     ah[2], al[2]);
                split_tf(Qs[kb + q + 4][m + 8], ah[3], al[3]);
                #pragma unroll
                for (int fn = 0; fn < 4; fn++) {
                    mma8(acc[fm][fn], ah[0], ah[1], ah[2], ah[3], bh[fn][0], bh[fn][1]);
                    mma8(acc[fm][fn], ah[0], ah[1], ah[2], ah[3], bl[fn][0], bl[fn][1]);
                    mma8(acc[fm][fn], al[0], al[1], al[2], al[3], bh[fn][0], bh[fn][1]);
                }
            }
        }
        __syncthreads();
    }

    float* Sb = S + (size_t)z * N_ * N_;
    #pragma unroll
    for (int fm = 0; fm < 4; fm++) {
        int rowA = row0 + wm * 64 + fm * 16 + g;
        #pragma unroll
        for (int fn = 0; fn < 4; fn++) {
            int col = col0 + wn * 32 + fn * 8 + 2 * q;
            float2 p0, p1;
            p0.x = acc[fm][fn][0] * 0.125f;
            p0.y = acc[fm][fn][1] * 0.125f;
            p1.x = acc[fm][fn][2] * 0.125f;
            p1.y = acc[fm][fn][3] * 0.125f;
            *(float2*)&Sb[(size_t)rowA * N_ + col] = p0;
            *(float2*)&Sb[(size_t)(rowA + 8) * N_ + col] = p1;
        }
    }
}

// ============ entmax bisect (alpha=1.5), in place =============================
// 30 iterations: remaining bracket 2.3e-10 < fp32 ulp of tau -> identical to 50.
__global__ void entmax_kernel(float* __restrict__ attn)
{
    int warp = threadIdx.x >> 5;
    int lane = threadIdx.x & 31;
    size_t row = (size_t)blockIdx.x * 8 + warp;
    float* S = attn + row * N_;

    float xa[32];
    float mx = -INFINITY;
    #pragma unroll
    for (int i = 0; i < 32; i++) {
        float v = S[i * 32 + lane] * 0.5f;
        xa[i] = v;
        mx = fmaxf(mx, v);
    }
    #pragma unroll
    for (int o = 16; o; o >>= 1)
        mx = fmaxf(mx, __shfl_xor_sync(0xFFFFFFFFu, mx, o));

    float tau_lo = mx - 1.0f;
    float dm = 1.0f - 0.03125f;

    float f_lo = 0.0f;
    #pragma unroll
    for (int i = 0; i < 32; i++) {
        float t = fmaxf(xa[i] - tau_lo, 0.0f);
        f_lo = fmaf(t, t, f_lo);
    }
    #pragma unroll
    for (int o = 16; o; o >>= 1)
        f_lo += __shfl_xor_sync(0xFFFFFFFFu, f_lo, o);
    f_lo -= 1.0f;

    float tau_m = tau_lo;
    for (int it = 0; it < 30; it++) {
        dm *= 0.5f;
        tau_m = tau_lo + dm;
        float f = 0.0f;
        #pragma unroll
        for (int i = 0; i < 32; i++) {
            float t = fmaxf(xa[i] - tau_m, 0.0f);
            f = fmaf(t, t, f);
        }
        #pragma unroll
        for (int o = 16; o; o >>= 1)
            f += __shfl_xor_sync(0xFFFFFFFFu, f, o);
        f -= 1.0f;
        if (f * f_lo >= 0.0f) tau_lo = tau_m;
    }

    float p[32];
    float s = 0.0f;
    #pragma unroll
    for (int i = 0; i < 32; i++) {
        float t = fmaxf(xa[i] - tau_m, 0.0f);
        p[i] = t * t;
        s += p[i];
    }
    #pragma unroll
    for (int o = 16; o; o >>= 1)
        s += __shfl_xor_sync(0xFFFFFFFFu, s, o);
    float inv = 1.0f / s;

    #pragma unroll
    for (int i = 0; i < 32; i++)
        S[i * 32 + lane] = p[i] * inv;
}

// ============ ctx = attn @ V per (b,h): 128x64 CTA, 32x32 warps (3xTF32) ======
__global__ void __launch_bounds__(256, 2)
attnv_kernel(const float* __restrict__ Attn, const float* __restrict__ V,
             float* __restrict__ ctx)
{
    __shared__ float As[32][132];   // [k][m]  (attn transposed)
    __shared__ float Vs[32][68];    // [k][d]

    int z = blockIdx.z;
    int bb = z >> 4, h = z & 15;
    const float* Ab = Attn + (size_t)z * N_ * N_;
    const float* Vb = V    + (size_t)z * N_ * DH;

    int tid = threadIdx.x;
    int lane = tid & 31, wid = tid >> 5;
    int g = lane >> 2, q = lane & 3;
    int wm = wid >> 1, wn = wid & 1;          // warps 4x2, warp tile 32x32
    int row0 = blockIdx.y * 128;

    float acc[2][4][4] = {};

    for (int k0 = 0; k0 < N_; k0 += 32) {
        #pragma unroll
        for (int i = 0; i < 4; i++) {
            int idx = tid + i * 256;
            int r = idx >> 3, c4 = (idx & 7) * 4;
            float4 a = *(const float4*)&Ab[(size_t)(row0 + r) * N_ + k0 + c4];
            As[c4 + 0][r] = a.x; As[c4 + 1][r] = a.y;
            As[c4 + 2][r] = a.z; As[c4 + 3][r] = a.w;
        }
        #pragma unroll
        for (int i = 0; i < 2; i++) {
            int idx = tid + i * 256;
            int r = idx >> 4, c4 = (idx & 15) * 4;
            *(float4*)&Vs[r][c4] = *(const float4*)&Vb[(size_t)(k0 + r) * DH + c4];
        }
        __syncthreads();

        #pragma unroll
        for (int ks = 0; ks < 4; ks++) {
            int kb = ks * 8;
            uint32_t bh[4][2], bl[4][2];
            #pragma unroll
            for (int fn = 0; fn < 4; fn++) {
                int col = wn * 32 + fn * 8 + g;
                split_tf(Vs[kb + q][col],     bh[fn][0], bl[fn][0]);
                split_tf(Vs[kb + q + 4][col], bh[fn][1], bl[fn][1]);
            }
            #pragma unroll
            for (int fm = 0; fm < 2; fm++) {
                int m = wm * 32 + fm * 16 + g;
                uint32_t ah[4], al[4];
                split_tf(As[kb + q][m],         ah[0], al[0]);
                split_tf(As[kb + q][m + 8],     ah[1], al[1]);
                split_tf(As[kb + q + 4][m],     ah[2], al[2]);
                split_tf(As[kb + q + 4][m + 8], ah[3], al[3]);
                #pragma unroll
                for (int fn = 0; fn < 4; fn++) {
                    mma8(acc[fm][fn], ah[0], ah[1], ah[2], ah[3], bh[fn][0], bh[fn][1]);
                    mma8(acc[fm][fn], ah[0], ah[1], ah[2], ah[3], bl[fn][0], bl[fn][1]);
                    mma8(acc[fm][fn], al[0], al[1], al[2], al[3], bh[fn][0], bh[fn][1]);
                }
            }
        }
        __syncthreads();
    }

    #pragma unroll
    for (int fm = 0; fm < 2; fm++) {
        int n = row0 + wm * 32 + fm * 16 + g;
        #pragma unroll
        for (int fn = 0; fn < 4; fn++) {
            int d = wn * 32 + fn * 8 + 2 * q;
            float2 p0, p1;
            p0.x = acc[fm][fn][0]; p0.y = acc[fm][fn][1];
            p1.x = acc[fm][fn][2]; p1.y = acc[fm][fn][3];
            *(float2*)&ctx[((size_t)bb * N_ + n) * C_ + h * DH + d] = p0;
            *(float2*)&ctx[((size_t)bb * N_ + n + 8) * C_ + h * DH + d] = p1;
        }
    }
}

// ============ launcher ========================================================
extern "C" void kernel_launch(void* const* d_in, const int* in_sizes, int n_in,
                              void* d_out, int out_size)
{
    const float* x  = (const float*)d_in[0];
    const float* Wq = (const float*)d_in[1];
    const float* bq = (const float*)d_in[2];
    const float* Wk = (const float*)d_in[3];
    const float* bk = (const float*)d_in[4];
    const float* Wv = (const float*)d_in[5];
    const float* bv = (const float*)d_in[6];
    const float* Wo = (const float*)d_in[7];
    const float* bo = (const float*)d_in[8];

    float* out = (float*)d_out;
    const size_t attn_elems = (size_t)B_ * H_ * N_ * N_;
    float* attn = out + ((size_t)out_size - attn_elems);

    float *q, *k, *v, *ctx;
    cudaGetSymbolAddress((void**)&q,   g_q);
    cudaGetSymbolAddress((void**)&k,   g_k);
    cudaGetSymbolAddress((void**)&v,   g_v);
    cudaGetSymbolAddress((void**)&ctx, g_ctx);

    dim3 blk(256);

    qkv_kernel<<<dim3(8, 32, 3), blk>>>(x, Wq, bq, Wk, bk, Wv, bv, q, k, v);
    scores_kernel<<<dim3(8, 8, BH), blk>>>(q, k, attn);
    entmax_kernel<<<dim3(ROWS / 8), blk>>>(attn);
    attnv_kernel<<<dim3(1, 8, BH), blk>>>(attn, v, ctx);
    proj_kernel<<<dim3(8, 32), blk>>>(ctx, Wo, bo, out);
}

// round 4
// speedup vs baseline: 2.2282x; 1.0653x over previous
#include <cuda_runtime.h>
#include <math.h>
#include <stdint.h>

#define B_  4
#define N_  1024
#define C_  1024
#define H_  16
#define DH  64
#define BH  (B_*H_)
#define ROWS (BH*N_)

// ---------------- scratch -----------------------------------------------------
__device__ float g_q[(size_t)B_*H_*N_*DH];
__device__ float g_k[(size_t)B_*H_*N_*DH];
__device__ float g_v[(size_t)B_*H_*N_*DH];
__device__ float g_ctx[(size_t)B_*N_*C_];

// ---------------- tf32 helpers ------------------------------------------------
__device__ __forceinline__ float tf_hi(float x) {
    uint32_t r;
    asm("cvt.rna.tf32.f32 %0, %1;" : "=r"(r) : "f"(x));
    return __uint_as_float(r);
}
__device__ __forceinline__ void split4(float4 v, float4& hi, float4& lo) {
    hi.x = tf_hi(v.x); lo.x = v.x - hi.x;
    hi.y = tf_hi(v.y); lo.y = v.y - hi.y;
    hi.z = tf_hi(v.z); lo.z = v.z - hi.z;
    hi.w = tf_hi(v.w); lo.w = v.w - hi.w;
}
__device__ __forceinline__ void mma8(float c[4],
                                     uint32_t a0, uint32_t a1, uint32_t a2, uint32_t a3,
                                     uint32_t b0, uint32_t b1) {
    asm("mma.sync.aligned.m16n8k8.row.col.f32.tf32.tf32.f32 "
        "{%0,%1,%2,%3},{%4,%5,%6,%7},{%8,%9},{%0,%1,%2,%3};"
        : "+f"(c[0]), "+f"(c[1]), "+f"(c[2]), "+f"(c[3])
        : "r"(a0), "r"(a1), "r"(a2), "r"(a3), "r"(b0), "r"(b1));
}
#define U(x) __float_as_uint(x)

// ============ 128x128 CTA, 64x32 warp tiles, 3xTF32, pipelined ================
// A: [4096 x 1024] rm, W: [1024 x 1024] rm. head_mode=1 -> [B,H,N,Dh] scatter.
__device__ __forceinline__ void gemm_tc_body(const float* __restrict__ A,
                                             const float* __restrict__ W,
                                             const float* __restrict__ bias,
                                             float* __restrict__ C,
                                             int head_mode)
{
    __shared__ float Ah[128][20], Al[128][20];    // [m][k], stride 20
    __shared__ float Bh[16][136], Bl[16][136];    // [k][n], stride 136

    const int K = C_, Nn = C_;
    int tid = threadIdx.x;
    int lane = tid & 31, wid = tid >> 5;
    int g = lane >> 2, qq = lane & 3;
    int wm = wid >> 2, wn = wid & 3;
    int row0 = blockIdx.y * 128;
    int col0 = blockIdx.x * 128;

    int ar = tid >> 2, ac = (tid & 3) * 4;        // A: rows ar, ar+64
    int br = tid >> 5, bc = (tid & 31) * 4;       // B: rows br, br+8

    float acc[4][4][4] = {};
    float4 pa[2], pb[2];

    #pragma unroll
    for (int i = 0; i < 2; i++) {
        pa[i] = *(const float4*)&A[(size_t)(row0 + ar + i * 64) * K + ac];
        pb[i] = *(const float4*)&W[(size_t)(br + i * 8) * Nn + col0 + bc];
    }

    const int NB = K / 16;
    for (int kb = 0; kb < NB; kb++) {
        #pragma unroll
        for (int i = 0; i < 2; i++) {
            float4 hi, lo;
            split4(pa[i], hi, lo);
            *(float4*)&Ah[ar + i * 64][ac] = hi;
            *(float4*)&Al[ar + i * 64][ac] = lo;
            split4(pb[i], hi, lo);
            *(float4*)&Bh[br + i * 8][bc] = hi;
            *(float4*)&Bl[br + i * 8][bc] = lo;
        }
        __syncthreads();

        if (kb + 1 < NB) {
            int k0 = (kb + 1) * 16;
            #pragma unroll
            for (int i = 0; i < 2; i++) {
                pa[i] = *(const float4*)&A[(size_t)(row0 + ar + i * 64) * K + k0 + ac];
                pb[i] = *(const float4*)&W[(size_t)(k0 + br + i * 8) * Nn + col0 + bc];
            }
        }

        #pragma unroll
        for (int ks = 0; ks < 2; ks++) {
            int k8 = ks * 8;
            uint32_t bhf[4][2], blf[4][2];
            #pragma unroll
            for (int fn = 0; fn < 4; fn++) {
                int col = wn * 32 + fn * 8 + g;
                bhf[fn][0] = U(Bh[k8 + qq][col]);
                bhf[fn][1] = U(Bh[k8 + qq + 4][col]);
                blf[fn][0] = U(Bl[k8 + qq][col]);
                blf[fn][1] = U(Bl[k8 + qq + 4][col]);
            }
            #pragma unroll
            for (int fm = 0; fm < 4; fm++) {
                int m = wm * 64 + fm * 16 + g;
                uint32_t ah[4], al[4];
                ah[0] = U(Ah[m][k8 + qq]);     ah[1] = U(Ah[m + 8][k8 + qq]);
                ah[2] = U(Ah[m][k8 + qq + 4]); ah[3] = U(Ah[m + 8][k8 + qq + 4]);
                al[0] = U(Al[m][k8 + qq]);     al[1] = U(Al[m + 8][k8 + qq]);
                al[2] = U(Al[m][k8 + qq + 4]); al[3] = U(Al[m + 8][k8 + qq + 4]);
                #pragma unroll
                for (int fn = 0; fn < 4; fn++) {
                    mma8(acc[fm][fn], ah[0], ah[1], ah[2], ah[3], bhf[fn][0], bhf[fn][1]);
                    mma8(acc[fm][fn], ah[0], ah[1], ah[2], ah[3], blf[fn][0], blf[fn][1]);
                    mma8(acc[fm][fn], al[0], al[1], al[2], al[3], bhf[fn][0], bhf[fn][1]);
                }
            }
        }
        __syncthreads();
    }

    #pragma unroll
    for (int fm = 0; fm < 4; fm++) {
        int rowA = row0 + wm * 64 + fm * 16 + g;
        #pragma unroll
        for (int fn = 0; fn < 4; fn++) {
            int col = col0 + wn * 32 + fn * 8 + 2 * qq;
            float2 p0, p1;
            p0.x = acc[fm][fn][0] + bias[col];
            p0.y = acc[fm][fn][1] + bias[col + 1];
            p1.x = acc[fm][fn][2] + bias[col];
            p1.y = acc[fm][fn][3] + bias[col + 1];
            if (head_mode) {
                int h = col >> 6, d = col & 63;
                int bb0 = rowA >> 10, n0 = rowA & 1023;
                int bb1 = (rowA + 8) >> 10, n1 = (rowA + 8) & 1023;
                *(float2*)&C[(((size_t)bb0 * H_ + h) * N_ + n0) * DH + d] = p0;
                *(float2*)&C[(((size_t)bb1 * H_ + h) * N_ + n1) * DH + d] = p1;
            } else {
                *(float2*)&C[(size_t)rowA * Nn + col] = p0;
                *(float2*)&C[(size_t)(rowA + 8) * Nn + col] = p1;
            }
        }
    }
}

__global__ void __launch_bounds__(256, 2)
qkv_kernel(const float* __restrict__ x,
           const float* __restrict__ Wq, const float* __restrict__ bq,
           const float* __restrict__ Wk, const float* __restrict__ bk,
           const float* __restrict__ Wv, const float* __restrict__ bv,
           float* __restrict__ q, float* __restrict__ k, float* __restrict__ v)
{
    int z = blockIdx.z;
    if (z == 0)      gemm_tc_body(x, Wq, bq, q, 1);
    else if (z == 1) gemm_tc_body(x, Wk, bk, k, 1);
    else             gemm_tc_body(x, Wv, bv, v, 1);
}

__global__ void __launch_bounds__(256, 2)
proj_kernel(const float* __restrict__ A, const float* __restrict__ W,
            const float* __restrict__ bias, float* __restrict__ C)
{
    gemm_tc_body(A, W, bias, C, 0);
}

// ============ scores: per (b,h), S = Q @ K^T * 0.125 ==========================
__global__ void __launch_bounds__(256, 2)
scores_kernel(const float* __restrict__ Q, const float* __restrict__ Km,
              float* __restrict__ S)
{
    __shared__ float Qh[128][20], Ql[128][20];    // [m][k]
    __shared__ float Kh[128][20], Kl[128][20];    // [n][k]

    int z = blockIdx.z;
    const float* Qb = Q  + (size_t)z * N_ * DH;
    const float* Kb = Km + (size_t)z * N_ * DH;

    int tid = threadIdx.x;
    int lane = tid & 31, wid = tid >> 5;
    int g = lane >> 2, qq = lane & 3;
    int wm = wid >> 2, wn = wid & 3;
    int row0 = blockIdx.y * 128;
    int col0 = blockIdx.x * 128;

    int ar = tid >> 2, ac = (tid & 3) * 4;

    float acc[4][4][4] = {};
    float4 pq[2], pk[2];

    #pragma unroll
    for (int i = 0; i < 2; i++) {
        pq[i] = *(const float4*)&Qb[(size_t)(row0 + ar + i * 64) * DH + ac];
        pk[i] = *(const float4*)&Kb[(size_t)(col0 + ar + i * 64) * DH + ac];
    }

    const int NB = DH / 16;   // 4
    #pragma unroll
    for (int kb = 0; kb < NB; kb++) {
        #pragma unroll
        for (int i = 0; i < 2; i++) {
            float4 hi, lo;
            split4(pq[i], hi, lo);
            *(float4*)&Qh[ar + i * 64][ac] = hi;
            *(float4*)&Ql[ar + i * 64][ac] = lo;
            split4(pk[i], hi, lo);
            *(float4*)&Kh[ar + i * 64][ac] = hi;
            *(float4*)&Kl[ar + i * 64][ac] = lo;
        }
        __syncthreads();

        if (kb + 1 < NB) {
            int k0 = (kb + 1) * 16;
            #pragma unroll
            for (int i = 0; i < 2; i++) {
                pq[i] = *(const float4*)&Qb[(size_t)(row0 + ar + i * 64) * DH + k0 + ac];
                pk[i] = *(const float4*)&Kb[(size_t)(col0 + ar + i * 64) * DH + k0 + ac];
            }
        }

        #pragma unroll
        for (int ks = 0; ks < 2; ks++) {
            int k8 = ks * 8;
            uint32_t bhf[4][2], blf[4][2];
            #pragma unroll
            for (int fn = 0; fn < 4; fn++) {
                int col = wn * 32 + fn * 8 + g;
                bhf[fn][0] = U(Kh[col][k8 + qq]);
                bhf[fn][1] = U(Kh[col][k8 + qq + 4]);
                blf[fn][0] = U(Kl[col][k8 + qq]);
                blf[fn][1] = U(Kl[col][k8 + qq + 4]);
            }
            #pragma unroll
            for (int fm = 0; fm < 4; fm++) {
                int m = wm * 64 + fm * 16 + g;
                uint32_t ah[4], al[4];
                ah[0] = U(Qh[m][k8 + qq]);     ah[1] = U(Qh[m + 8][k8 + qq]);
                ah[2] = U(Qh[m][k8 + qq + 4]); ah[3] = U(Qh[m + 8][k8 + qq + 4]);
                al[0] = U(Ql[m][k8 + qq]);     al[1] = U(Ql[m + 8][k8 + qq]);
                al[2] = U(Ql[m][k8 + qq + 4]); al[3] = U(Ql[m + 8][k8 + qq + 4]);
                #pragma unroll
                for (int fn = 0; fn < 4; fn++) {
                    mma8(acc[fm][fn], ah[0], ah[1], ah[2], ah[3], bhf[fn][0], bhf[fn][1]);
                    mma8(acc[fm][fn], ah[0], ah[1], ah[2], ah[3], blf[fn][0], blf[fn][1]);
                    mma8(acc[fm][fn], al[0], al[1], al[2], al[3], bhf[fn][0], bhf[fn][1]);
                }
            }
        }
        __syncthreads();
    }

    float* Sb = S + (size_t)z * N_ * N_;
    #pragma unroll
    for (int fm = 0; fm < 4; fm++) {
        int rowA = row0 + wm * 64 + fm * 16 + g;
        #pragma unroll
        for (int fn = 0; fn < 4; fn++) {
            int col = col0 + wn * 32 + fn * 8 + 2 * qq;
            float2 p0, p1;
            p0.x = acc[fm][fn][0] * 0.125f;
            p0.y = acc[fm][fn][1] * 0.125f;
            p1.x = acc[fm][fn][2] * 0.125f;
            p1.y = acc[fm][fn][3] * 0.125f;
            *(float2*)&Sb[(size_t)rowA * N_ + col] = p0;
            *(float2*)&Sb[(size_t)(rowA + 8) * N_ + col] = p1;
        }
    }
}

// ============ entmax bisect (alpha=1.5, 30 iters), in place ===================
__global__ void entmax_kernel(float* __restrict__ attn)
{
    int warp = threadIdx.x >> 5;
    int lane = threadIdx.x & 31;
    size_t row = (size_t)blockIdx.x * 8 + warp;
    float* S = attn + row * N_;

    float xa[32];
    float mx = -INFINITY;
    #pragma unroll
    for (int i = 0; i < 32; i++) {
        float v = S[i * 32 + lane] * 0.5f;
        xa[i] = v;
        mx = fmaxf(mx, v);
    }
    #pragma unroll
    for (int o = 16; o; o >>= 1)
        mx = fmaxf(mx, __shfl_xor_sync(0xFFFFFFFFu, mx, o));

    float tau_lo = mx - 1.0f;
    float dm = 1.0f - 0.03125f;

    float f_lo = 0.0f;
    #pragma unroll
    for (int i = 0; i < 32; i++) {
        float t = fmaxf(xa[i] - tau_lo, 0.0f);
        f_lo = fmaf(t, t, f_lo);
    }
    #pragma unroll
    for (int o = 16; o; o >>= 1)
        f_lo += __shfl_xor_sync(0xFFFFFFFFu, f_lo, o);
    f_lo -= 1.0f;

    float tau_m = tau_lo;
    for (int it = 0; it < 30; it++) {
        dm *= 0.5f;
        tau_m = tau_lo + dm;
        float f = 0.0f;
        #pragma unroll
        for (int i = 0; i < 32; i++) {
            float t = fmaxf(xa[i] - tau_m, 0.0f);
            f = fmaf(t, t, f);
        }
        #pragma unroll
        for (int o = 16; o; o >>= 1)
            f += __shfl_xor_sync(0xFFFFFFFFu, f, o);
        f -= 1.0f;
        if (f * f_lo >= 0.0f) tau_lo = tau_m;
    }

    float p[32];
    float s = 0.0f;
    #pragma unroll
    for (int i = 0; i < 32; i++) {
        float t = fmaxf(xa[i] - tau_m, 0.0f);
        p[i] = t * t;
        s += p[i];
    }
    #pragma unroll
    for (int o = 16; o; o >>= 1)
        s += __shfl_xor_sync(0xFFFFFFFFu, s, o);
    float inv = 1.0f / s;

    #pragma unroll
    for (int i = 0; i < 32; i++)
        S[i * 32 + lane] = p[i] * inv;
}

// ============ ctx = attn @ V per (b,h): 128x64 CTA, 32x32 warps ===============
__global__ void __launch_bounds__(256, 2)
attnv_kernel(const float* __restrict__ Attn, const float* __restrict__ V,
             float* __restrict__ ctx)
{
    __shared__ float Ah[128][20], Al[128][20];    // [m][k]
    __shared__ float Vh[16][72],  Vl[16][72];     // [k][d]

    int z = blockIdx.z;
    int bb = z >> 4, h = z & 15;
    const float* Ab = Attn + (size_t)z * N_ * N_;
    const float* Vb = V    + (size_t)z * N_ * DH;

    int tid = threadIdx.x;
    int lane = tid & 31, wid = tid >> 5;
    int g = lane >> 2, qq = lane & 3;
    int wm = wid >> 1, wn = wid & 1;              // warps 4x2, tile 32x32
    int row0 = blockIdx.y * 128;

    int ar = tid >> 2, ac = (tid & 3) * 4;
    int vr = tid >> 4, vc = (tid & 15) * 4;

    float acc[2][4][4] = {};
    float4 pa[2], pv;

    #pragma unroll
    for (int i = 0; i < 2; i++)
        pa[i] = *(const float4*)&Ab[(size_t)(row0 + ar + i * 64) * N_ + ac];
    pv = *(const float4*)&Vb[(size_t)vr * DH + vc];

    const int NB = N_ / 16;
    for (int kb = 0; kb < NB; kb++) {
        #pragma unroll
        for (int i = 0; i < 2; i++) {
            float4 hi, lo;
            split4(pa[i], hi, lo);
            *(float4*)&Ah[ar + i * 64][ac] = hi;
            *(float4*)&Al[ar + i * 64][ac] = lo;
        }
        {
            float4 hi, lo;
            split4(pv, hi, lo);
            *(float4*)&Vh[vr][vc] = hi;
            *(float4*)&Vl[vr][vc] = lo;
        }
        __syncthreads();

        if (kb + 1 < NB) {
            int k0 = (kb + 1) * 16;
            #pragma unroll
            for (int i = 0; i < 2; i++)
                pa[i] = *(const float4*)&Ab[(size_t)(row0 + ar + i * 64) * N_ + k0 + ac];
            pv = *(const float4*)&Vb[(size_t)(k0 + vr) * DH + vc];
        }

        #pragma unroll
        for (int ks = 0; ks < 2; ks++) {
            int k8 = ks * 8;
            uint32_t bhf[4][2], blf[4][2];
            #pragma unroll
            for (int fn = 0; fn < 4; fn++) {
                int col = wn * 32 + fn * 8 + g;
                bhf[fn][0] = U(Vh[k8 + qq][col]);
                bhf[fn][1] = U(Vh[k8 + qq + 4][col]);
                blf[fn][0] = U(Vl[k8 + qq][col]);
                blf[fn][1] = U(Vl[k8 + qq + 4][col]);
            }
            #pragma unroll
            for (int fm = 0; fm < 2; fm++) {
                int m = wm * 32 + fm * 16 + g;
                uint32_t ah[4], al[4];
                ah[0] = U(Ah[m][k8 + qq]);     ah[1] = U(Ah[m + 8][k8 + qq]);
                ah[2] = U(Ah[m][k8 + qq + 4]); ah[3] = U(Ah[m + 8][k8 + qq + 4]);
                al[0] = U(Al[m][k8 + qq]);     al[1] = U(Al[m + 8][k8 + qq]);
                al[2] = U(Al[m][k8 + qq + 4]); al[3] = U(Al[m + 8][k8 + qq + 4]);
                #pragma unroll
                for (int fn = 0; fn < 4; fn++) {
                    mma8(acc[fm][fn], ah[0], ah[1], ah[2], ah[3], bhf[fn][0], bhf[fn][1]);
                    mma8(acc[fm][fn], ah[0], ah[1], ah[2], ah[3], blf[fn][0], blf[fn][1]);
                    mma8(acc[fm][fn], al[0], al[1], al[2], al[3], bhf[fn][0], bhf[fn][1]);
                }
            }
        }
        __syncthreads();
    }

    #pragma unroll
    for (int fm = 0; fm < 2; fm++) {
        int n = row0 + wm * 32 + fm * 16 + g;
        #pragma unroll
        for (int fn = 0; fn < 4; fn++) {
            int d = wn * 32 + fn * 8 + 2 * qq;
            float2 p0, p1;
            p0.x = acc[fm][fn][0]; p0.y = acc[fm][fn][1];
            p1.x = acc[fm][fn][2]; p1.y = acc[fm][fn][3];
            *(float2*)&ctx[((size_t)bb * N_ + n) * C_ + h * DH + d] = p0;
            *(float2*)&ctx[((size_t)bb * N_ + n + 8) * C_ + h * DH + d] = p1;
        }
    }
}

// ============ launcher ========================================================
extern "C" void kernel_launch(void* const* d_in, const int* in_sizes, int n_in,
                              void* d_out, int out_size)
{
    const float* x  = (const float*)d_in[0];
    const float* Wq = (const float*)d_in[1];
    const float* bq = (const float*)d_in[2];
    const float* Wk = (const float*)d_in[3];
    const float* bk = (const float*)d_in[4];
    const float* Wv = (const float*)d_in[5];
    const float* bv = (const float*)d_in[6];
    const float* Wo = (const float*)d_in[7];
    const float* bo = (const float*)d_in[8];

    float* out = (float*)d_out;
    const size_t attn_elems = (size_t)B_ * H_ * N_ * N_;
    float* attn = out + ((size_t)out_size - attn_elems);

    float *q, *k, *v, *ctx;
    cudaGetSymbolAddress((void**)&q,   g_q);
    cudaGetSymbolAddress((void**)&k,   g_k);
    cudaGetSymbolAddress((void**)&v,   g_v);
    cudaGetSymbolAddress((void**)&ctx, g_ctx);

    dim3 blk(256);

    qkv_kernel<<<dim3(8, 32, 3), blk>>>(x, Wq, bq, Wk, bk, Wv, bv, q, k, v);
    scores_kernel<<<dim3(8, 8, BH), blk>>>(q, k, attn);
    entmax_kernel<<<dim3(ROWS / 8), blk>>>(attn);
    attnv_kernel<<<dim3(1, 8, BH), blk>>>(attn, v, ctx);
    proj_kernel<<<dim3(8, 32), blk>>>(ctx, Wo, bo, out);
}

// round 5
// speedup vs baseline: 2.5328x; 1.1367x over previous
#include <cuda_runtime.h>
#include <math.h>
#include <stdint.h>

#define B_  4
#define N_  1024
#define C_  1024
#define H_  16
#define DH  64
#define BH  (B_*H_)
#define ROWS (BH*N_)

// ---------------- scratch -----------------------------------------------------
__device__ float g_q[(size_t)B_*H_*N_*DH];
__device__ float g_k[(size_t)B_*H_*N_*DH];
__device__ float g_v[(size_t)B_*H_*N_*DH];
__device__ float g_ctx[(size_t)B_*N_*C_];

// ---------------- tf32 helpers ------------------------------------------------
__device__ __forceinline__ float tf_hi(float x) {
    uint32_t r;
    asm("cvt.rna.tf32.f32 %0, %1;" : "=r"(r) : "f"(x));
    return __uint_as_float(r);
}
__device__ __forceinline__ void split4(float4 v, float4& hi, float4& lo) {
    hi.x = tf_hi(v.x); lo.x = v.x - hi.x;
    hi.y = tf_hi(v.y); lo.y = v.y - hi.y;
    hi.z = tf_hi(v.z); lo.z = v.z - hi.z;
    hi.w = tf_hi(v.w); lo.w = v.w - hi.w;
}
__device__ __forceinline__ void mma8(float c[4],
                                     uint32_t a0, uint32_t a1, uint32_t a2, uint32_t a3,
                                     uint32_t b0, uint32_t b1) {
    asm("mma.sync.aligned.m16n8k8.row.col.f32.tf32.tf32.f32 "
        "{%0,%1,%2,%3},{%4,%5,%6,%7},{%8,%9},{%0,%1,%2,%3};"
        : "+f"(c[0]), "+f"(c[1]), "+f"(c[2]), "+f"(c[3])
        : "r"(a0), "r"(a1), "r"(a2), "r"(a3), "r"(b0), "r"(b1));
}
#define U(x) __float_as_uint(x)

// ---------------- bf16 split helpers (for output-path GEMMs) ------------------
// x = hi + lo: hi = top-16-bit truncation (exact bf16), lo = rn-bf16 of residual.
// pair (even -> low half, odd -> high half) to match m16n8k16 fragment layout.
__device__ __forceinline__ void split_pair_bf16(float ve, float vo,
                                                uint32_t& hi, uint32_t& lo) {
    uint32_t ue = __float_as_uint(ve), uo = __float_as_uint(vo);
    hi = __byte_perm(ue, uo, 0x7632);
    float he = __uint_as_float(ue & 0xFFFF0000u);
    float ho = __uint_as_float(uo & 0xFFFF0000u);
    float le = ve - he;
    float lof = vo - ho;
    asm("cvt.rn.bf16x2.f32 %0, %1, %2;" : "=r"(lo) : "f"(lof), "f"(le));
}
__device__ __forceinline__ void mma16(float c[4],
                                      uint32_t a0, uint32_t a1, uint32_t a2, uint32_t a3,
                                      uint32_t b0, uint32_t b1) {
    asm("mma.sync.aligned.m16n8k16.row.col.f32.bf16.bf16.f32 "
        "{%0,%1,%2,%3},{%4,%5,%6,%7},{%8,%9},{%0,%1,%2,%3};"
        : "+f"(c[0]), "+f"(c[1]), "+f"(c[2]), "+f"(c[3])
        : "r"(a0), "r"(a1), "r"(a2), "r"(a3), "r"(b0), "r"(b1));
}

// ============ qkv: 128x128 CTA, 64x32 warp tiles, 3xTF32, pipelined ===========
__device__ __forceinline__ void gemm_tc_body(const float* __restrict__ A,
                                             const float* __restrict__ W,
                                             const float* __restrict__ bias,
                                             float* __restrict__ C)
{
    __shared__ float Ah[128][20], Al[128][20];
    __shared__ float Bh[16][136], Bl[16][136];

    const int K = C_, Nn = C_;
    int tid = threadIdx.x;
    int lane = tid & 31, wid = tid >> 5;
    int g = lane >> 2, qq = lane & 3;
    int wm = wid >> 2, wn = wid & 3;
    int row0 = blockIdx.y * 128;
    int col0 = blockIdx.x * 128;

    int ar = tid >> 2, ac = (tid & 3) * 4;
    int br = tid >> 5, bc = (tid & 31) * 4;

    float acc[4][4][4] = {};
    float4 pa[2], pb[2];

    #pragma unroll
    for (int i = 0; i < 2; i++) {
        pa[i] = *(const float4*)&A[(size_t)(row0 + ar + i * 64) * K + ac];
        pb[i] = *(const float4*)&W[(size_t)(br + i * 8) * Nn + col0 + bc];
    }

    const int NB = K / 16;
    for (int kb = 0; kb < NB; kb++) {
        #pragma unroll
        for (int i = 0; i < 2; i++) {
            float4 hi, lo;
            split4(pa[i], hi, lo);
            *(float4*)&Ah[ar + i * 64][ac] = hi;
            *(float4*)&Al[ar + i * 64][ac] = lo;
            split4(pb[i], hi, lo);
            *(float4*)&Bh[br + i * 8][bc] = hi;
            *(float4*)&Bl[br + i * 8][bc] = lo;
        }
        __syncthreads();

        if (kb + 1 < NB) {
            int k0 = (kb + 1) * 16;
            #pragma unroll
            for (int i = 0; i < 2; i++) {
                pa[i] = *(const float4*)&A[(size_t)(row0 + ar + i * 64) * K + k0 + ac];
                pb[i] = *(const float4*)&W[(size_t)(k0 + br + i * 8) * Nn + col0 + bc];
            }
        }

        #pragma unroll
        for (int ks = 0; ks < 2; ks++) {
            int k8 = ks * 8;
            uint32_t bhf[4][2], blf[4][2];
            #pragma unroll
            for (int fn = 0; fn < 4; fn++) {
                int col = wn * 32 + fn * 8 + g;
                bhf[fn][0] = U(Bh[k8 + qq][col]);
                bhf[fn][1] = U(Bh[k8 + qq + 4][col]);
                blf[fn][0] = U(Bl[k8 + qq][col]);
                blf[fn][1] = U(Bl[k8 + qq + 4][col]);
            }
            #pragma unroll
            for (int fm = 0; fm < 4; fm++) {
                int m = wm * 64 + fm * 16 + g;
                uint32_t ah[4], al[4];
                ah[0] = U(Ah[m][k8 + qq]);     ah[1] = U(Ah[m + 8][k8 + qq]);
                ah[2] = U(Ah[m][k8 + qq + 4]); ah[3] = U(Ah[m + 8][k8 + qq + 4]);
                al[0] = U(Al[m][k8 + qq]);     al[1] = U(Al[m + 8][k8 + qq]);
                al[2] = U(Al[m][k8 + qq + 4]); al[3] = U(Al[m + 8][k8 + qq + 4]);
                #pragma unroll
                for (int fn = 0; fn < 4; fn++)
                    mma8(acc[fm][fn], ah[0], ah[1], ah[2], ah[3], bhf[fn][0], bhf[fn][1]);
                #pragma unroll
                for (int fn = 0; fn < 4; fn++)
                    mma8(acc[fm][fn], ah[0], ah[1], ah[2], ah[3], blf[fn][0], blf[fn][1]);
                #pragma unroll
                for (int fn = 0; fn < 4; fn++)
                    mma8(acc[fm][fn], al[0], al[1], al[2], al[3], bhf[fn][0], bhf[fn][1]);
            }
        }
        __syncthreads();
    }

    #pragma unroll
    for (int fm = 0; fm < 4; fm++) {
        int rowA = row0 + wm * 64 + fm * 16 + g;
        #pragma unroll
        for (int fn = 0; fn < 4; fn++) {
            int col = col0 + wn * 32 + fn * 8 + 2 * qq;
            float2 p0, p1;
            p0.x = acc[fm][fn][0] + bias[col];
            p0.y = acc[fm][fn][1] + bias[col + 1];
            p1.x = acc[fm][fn][2] + bias[col];
            p1.y = acc[fm][fn][3] + bias[col + 1];
            int h = col >> 6, d = col & 63;
            int bb0 = rowA >> 10, n0 = rowA & 1023;
            int bb1 = (rowA + 8) >> 10, n1 = (rowA + 8) & 1023;
            *(float2*)&C[(((size_t)bb0 * H_ + h) * N_ + n0) * DH + d] = p0;
            *(float2*)&C[(((size_t)bb1 * H_ + h) * N_ + n1) * DH + d] = p1;
        }
    }
}

__global__ void __launch_bounds__(256, 2)
qkv_kernel(const float* __restrict__ x,
           const float* __restrict__ Wq, const float* __restrict__ bq,
           const float* __restrict__ Wk, const float* __restrict__ bk,
           const float* __restrict__ Wv, const float* __restrict__ bv,
           float* __restrict__ q, float* __restrict__ k, float* __restrict__ v)
{
    int z = blockIdx.z;
    if (z == 0)      gemm_tc_body(x, Wq, bq, q);
    else if (z == 1) gemm_tc_body(x, Wk, bk, k);
    else             gemm_tc_body(x, Wv, bv, v);
}

// ============ scores: per (b,h), S = Q @ K^T * 0.125 (3xTF32) =================
__global__ void __launch_bounds__(256, 2)
scores_kernel(const float* __restrict__ Q, const float* __restrict__ Km,
              float* __restrict__ S)
{
    __shared__ float Qh[128][20], Ql[128][20];
    __shared__ float Kh[128][20], Kl[128][20];

    int z = blockIdx.z;
    const float* Qb = Q  + (size_t)z * N_ * DH;
    const float* Kb = Km + (size_t)z * N_ * DH;

    int tid = threadIdx.x;
    int lane = tid & 31, wid = tid >> 5;
    int g = lane >> 2, qq = lane & 3;
    int wm = wid >> 2, wn = wid & 3;
    int row0 = blockIdx.y * 128;
    int col0 = blockIdx.x * 128;

    int ar = tid >> 2, ac = (tid & 3) * 4;

    float acc[4][4][4] = {};
    float4 pq[2], pk[2];

    #pragma unroll
    for (int i = 0; i < 2; i++) {
        pq[i] = *(const float4*)&Qb[(size_t)(row0 + ar + i * 64) * DH + ac];
        pk[i] = *(const float4*)&Kb[(size_t)(col0 + ar + i * 64) * DH + ac];
    }

    const int NB = DH / 16;
    #pragma unroll
    for (int kb = 0; kb < NB; kb++) {
        #pragma unroll
        for (int i = 0; i < 2; i++) {
            float4 hi, lo;
            split4(pq[i], hi, lo);
            *(float4*)&Qh[ar + i * 64][ac] = hi;
            *(float4*)&Ql[ar + i * 64][ac] = lo;
            split4(pk[i], hi, lo);
            *(float4*)&Kh[ar + i * 64][ac] = hi;
            *(float4*)&Kl[ar + i * 64][ac] = lo;
        }
        __syncthreads();

        if (kb + 1 < NB) {
            int k0 = (kb + 1) * 16;
            #pragma unroll
            for (int i = 0; i < 2; i++) {
                pq[i] = *(const float4*)&Qb[(size_t)(row0 + ar + i * 64) * DH + k0 + ac];
                pk[i] = *(const float4*)&Kb[(size_t)(col0 + ar + i * 64) * DH + k0 + ac];
            }
        }

        #pragma unroll
        for (int ks = 0; ks < 2; ks++) {
            int k8 = ks * 8;
            uint32_t bhf[4][2], blf[4][2];
            #pragma unroll
            for (int fn = 0; fn < 4; fn++) {
                int col = wn * 32 + fn * 8 + g;
                bhf[fn][0] = U(Kh[col][k8 + qq]);
                bhf[fn][1] = U(Kh[col][k8 + qq + 4]);
                blf[fn][0] = U(Kl[col][k8 + qq]);
                blf[fn][1] = U(Kl[col][k8 + qq + 4]);
            }
            #pragma unroll
            for (int fm = 0; fm < 4; fm++) {
                int m = wm * 64 + fm * 16 + g;
                uint32_t ah[4], al[4];
                ah[0] = U(Qh[m][k8 + qq]);     ah[1] = U(Qh[m + 8][k8 + qq]);
                ah[2] = U(Qh[m][k8 + qq + 4]); ah[3] = U(Qh[m + 8][k8 + qq + 4]);
                al[0] = U(Ql[m][k8 + qq]);     al[1] = U(Ql[m + 8][k8 + qq]);
                al[2] = U(Ql[m][k8 + qq + 4]); al[3] = U(Ql[m + 8][k8 + qq + 4]);
                #pragma unroll
                for (int fn = 0; fn < 4; fn++)
                    mma8(acc[fm][fn], ah[0], ah[1], ah[2], ah[3], bhf[fn][0], bhf[fn][1]);
                #pragma unroll
                for (int fn = 0; fn < 4; fn++)
                    mma8(acc[fm][fn], ah[0], ah[1], ah[2], ah[3], blf[fn][0], blf[fn][1]);
                #pragma unroll
                for (int fn = 0; fn < 4; fn++)
                    mma8(acc[fm][fn], al[0], al[1], al[2], al[3], bhf[fn][0], bhf[fn][1]);
            }
        }
        __syncthreads();
    }

    float* Sb = S + (size_t)z * N_ * N_;
    #pragma unroll
    for (int fm = 0; fm < 4; fm++) {
        int rowA = row0 + wm * 64 + fm * 16 + g;
        #pragma unroll
        for (int fn = 0; fn < 4; fn++) {
            int col = col0 + wn * 32 + fn * 8 + 2 * qq;
            float2 p0, p1;
            p0.x = acc[fm][fn][0] * 0.125f;
            p0.y = acc[fm][fn][1] * 0.125f;
            p1.x = acc[fm][fn][2] * 0.125f;
            p1.y = acc[fm][fn][3] * 0.125f;
            *(float2*)&Sb[(size_t)rowA * N_ + col] = p0;
            *(float2*)&Sb[(size_t)(rowA + 8) * N_ + col] = p1;
        }
    }
}

// ============ entmax: 14 bisection iters + exact quadratic finish =============
__global__ void entmax_kernel(float* __restrict__ attn)
{
    int warp = threadIdx.x >> 5;
    int lane = threadIdx.x & 31;
    size_t row = (size_t)blockIdx.x * 8 + warp;
    float* S = attn + row * N_;

    float xa[32];
    float mx = -INFINITY;
    #pragma unroll
    for (int i = 0; i < 32; i++) {
        float v = S[i * 32 + lane] * 0.5f;
        xa[i] = v;
        mx = fmaxf(mx, v);
    }
    #pragma unroll
    for (int o = 16; o; o >>= 1)
        mx = fmaxf(mx, __shfl_xor_sync(0xFFFFFFFFu, mx, o));

    float tau_lo = mx - 1.0f;
    float dm = 1.0f - 0.03125f;

    float f_lo = 0.0f;
    #pragma unroll
    for (int i = 0; i < 32; i++) {
        float t = fmaxf(xa[i] - tau_lo, 0.0f);
        f_lo = fmaf(t, t, f_lo);
    }
    #pragma unroll
    for (int o = 16; o; o >>= 1)
        f_lo += __shfl_xor_sync(0xFFFFFFFFu, f_lo, o);
    f_lo -= 1.0f;

    for (int it = 0; it < 14; it++) {
        dm *= 0.5f;
        float tau_m = tau_lo + dm;
        float f = 0.0f;
        #pragma unroll
        for (int i = 0; i < 32; i++) {
            float t = fmaxf(xa[i] - tau_m, 0.0f);
            f = fmaf(t, t, f);
        }
        #pragma unroll
        for (int o = 16; o; o >>= 1)
            f += __shfl_xor_sync(0xFFFFFFFFu, f, o);
        f -= 1.0f;
        if (f * f_lo >= 0.0f) tau_lo = tau_m;
    }

    // Exact finish: on the (bracket-determined) support, f is quadratic:
    // k*tau^2 - 2*S1*tau + (S2 - 1) = 0; take the root below the support.
    int   cnt = 0;
    float S1 = 0.0f, S2 = 0.0f;
    #pragma unroll
    for (int i = 0; i < 32; i++) {
        if (xa[i] > tau_lo) {
            cnt += 1;
            S1 += xa[i];
            S2 = fmaf(xa[i], xa[i], S2);
        }
    }
    #pragma unroll
    for (int o = 16; o; o >>= 1) {
        cnt += __shfl_xor_sync(0xFFFFFFFFu, cnt, o);
        S1  += __shfl_xor_sync(0xFFFFFFFFu, S1, o);
        S2  += __shfl_xor_sync(0xFFFFFFFFu, S2, o);
    }
    float kf = (float)cnt;
    float disc = fmaxf(fmaf(S1, S1, -kf * (S2 - 1.0f)), 0.0f);
    float tau = (S1 - sqrtf(disc)) / kf;
    tau = fminf(fmaxf(tau, tau_lo), tau_lo + dm);

    float p[32];
    float s = 0.0f;
    #pragma unroll
    for (int i = 0; i < 32; i++) {
        float t = fmaxf(xa[i] - tau, 0.0f);
        p[i] = t * t;
        s += p[i];
    }
    #pragma unroll
    for (int o = 16; o; o >>= 1)
        s += __shfl_xor_sync(0xFFFFFFFFu, s, o);
    float inv = 1.0f / s;

    #pragma unroll
    for (int i = 0; i < 32; i++)
        S[i * 32 + lane] = p[i] * inv;
}

// ============ ctx = attn @ V per (b,h): 3x bf16 m16n8k16 ======================
// warps 4x2, warp tile 32x32; packed k-pairs in smem.
__global__ void __launch_bounds__(256, 2)
attnv_kernel(const float* __restrict__ Attn, const float* __restrict__ V,
             float* __restrict__ ctx)
{
    __shared__ uint32_t Ahs[128][12], Als[128][12];   // [m][kpair]
    __shared__ uint32_t Vhs[64][12],  Vls[64][12];    // [d][kpair]

    int z = blockIdx.z;
    int bb = z >> 4, h = z & 15;
    const float* Ab = Attn + (size_t)z * N_ * N_;
    const float* Vb = V    + (size_t)z * N_ * DH;

    int tid = threadIdx.x;
    int lane = tid & 31, wid = tid >> 5;
    int g = lane >> 2, qq = lane & 3;
    int wm = wid >> 1, wn = wid & 1;
    int row0 = blockIdx.y * 128;

    int ar = tid >> 2, ac = (tid & 3) * 4, c2 = (tid & 3) * 2;
    int rp = (tid & 127) >> 4, vc = (tid & 15) * 4;
    bool vload = tid < 128;

    float acc[2][4][4] = {};
    float4 pa[2], pv0, pv1;

    #pragma unroll
    for (int i = 0; i < 2; i++)
        pa[i] = *(const float4*)&Ab[(size_t)(row0 + ar + i * 64) * N_ + ac];
    if (vload) {
        pv0 = *(const float4*)&Vb[(size_t)(2 * rp) * DH + vc];
        pv1 = *(const float4*)&Vb[(size_t)(2 * rp + 1) * DH + vc];
    }

    const int NB = N_ / 16;
    for (int kb = 0; kb < NB; kb++) {
        #pragma unroll
        for (int i = 0; i < 2; i++) {
            uint32_t h0, l0, h1, l1;
            split_pair_bf16(pa[i].x, pa[i].y, h0, l0);
            split_pair_bf16(pa[i].z, pa[i].w, h1, l1);
            int r = ar + i * 64;
            Ahs[r][c2] = h0; Ahs[r][c2 + 1] = h1;
            Als[r][c2] = l0; Als[r][c2 + 1] = l1;
        }
        if (vload) {
            const float* e = (const float*)&pv0;
            const float* o = (const float*)&pv1;
            #pragma unroll
            for (int j = 0; j < 4; j++) {
                uint32_t hh, ll;
                split_pair_bf16(e[j], o[j], hh, ll);
                Vhs[vc + j][rp] = hh;
                Vls[vc + j][rp] = ll;
            }
        }
        __syncthreads();

        if (kb + 1 < NB) {
            int k0 = (kb + 1) * 16;
            #pragma unroll
            for (int i = 0; i < 2; i++)
                pa[i] = *(const float4*)&Ab[(size_t)(row0 + ar + i * 64) * N_ + k0 + ac];
            if (vload) {
                pv0 = *(const float4*)&Vb[(size_t)(k0 + 2 * rp) * DH + vc];
                pv1 = *(const float4*)&Vb[(size_t)(k0 + 2 * rp + 1) * DH + vc];
            }
        }

        uint32_t bh0[4], bh1[4], bl0[4], bl1[4];
        #pragma unroll
        for (int fn = 0; fn < 4; fn++) {
            int col = wn * 32 + fn * 8 + g;
            bh0[fn] = Vhs[col][qq];     bh1[fn] = Vhs[col][qq + 4];
            bl0[fn] = Vls[col][qq];     bl1[fn] = Vls[col][qq + 4];
        }
        #pragma unroll
        for (int fm = 0; fm < 2; fm++) {
            int m = wm * 32 + fm * 16 + g;
            uint32_t ah[4], al[4];
            ah[0] = Ahs[m][qq];     ah[1] = Ahs[m + 8][qq];
            ah[2] = Ahs[m][qq + 4]; ah[3] = Ahs[m + 8][qq + 4];
            al[0] = Als[m][qq];     al[1] = Als[m + 8][qq];
            al[2] = Als[m][qq + 4]; al[3] = Als[m + 8][qq + 4];
            #pragma unroll
            for (int fn = 0; fn < 4; fn++)
                mma16(acc[fm][fn], ah[0], ah[1], ah[2], ah[3], bh0[fn], bh1[fn]);
            #pragma unroll
            for (int fn = 0; fn < 4; fn++)
                mma16(acc[fm][fn], ah[0], ah[1], ah[2], ah[3], bl0[fn], bl1[fn]);
            #pragma unroll
            for (int fn = 0; fn < 4; fn++)
                mma16(acc[fm][fn], al[0], al[1], al[2], al[3], bh0[fn], bh1[fn]);
        }
        __syncthreads();
    }

    #pragma unroll
    for (int fm = 0; fm < 2; fm++) {
        int n = row0 + wm * 32 + fm * 16 + g;
        #pragma unroll
        for (int fn = 0; fn < 4; fn++) {
            int d = wn * 32 + fn * 8 + 2 * qq;
            float2 p0, p1;
            p0.x = acc[fm][fn][0]; p0.y = acc[fm][fn][1];
            p1.x = acc[fm][fn][2]; p1.y = acc[fm][fn][3];
            *(float2*)&ctx[((size_t)bb * N_ + n) * C_ + h * DH + d] = p0;
            *(float2*)&ctx[((size_t)bb * N_ + n + 8) * C_ + h * DH + d] = p1;
        }
    }
}

// ============ out proj: ctx @ Wo + bo, 3x bf16 m16n8k16 =======================
// warps 2x4, warp tile 64x32.
__global__ void __launch_bounds__(256, 2)
proj_kernel(const float* __restrict__ A, const float* __restrict__ W,
            const float* __restrict__ bias, float* __restrict__ C)
{
    __shared__ uint32_t Ahs[128][12], Als[128][12];   // [m][kpair]
    __shared__ uint32_t Whs[128][12], Wls[128][12];   // [n][kpair]

    const int K = C_, Nn = C_;
    int tid = threadIdx.x;
    int lane = tid & 31, wid = tid >> 5;
    int g = lane >> 2, qq = lane & 3;
    int wm = wid >> 2, wn = wid & 3;
    int row0 = blockIdx.y * 128;
    int col0 = blockIdx.x * 128;

    int ar = tid >> 2, ac = (tid & 3) * 4, c2 = (tid & 3) * 2;
    int rp = tid >> 5, wc = (tid & 31) * 4;

    float acc[4][4][4] = {};
    float4 pa[2], pw0, pw1;

    #pragma unroll
    for (int i = 0; i < 2; i++)
        pa[i] = *(const float4*)&A[(size_t)(row0 + ar + i * 64) * K + ac];
    pw0 = *(const float4*)&W[(size_t)(2 * rp) * Nn + col0 + wc];
    pw1 = *(const float4*)&W[(size_t)(2 * rp + 1) * Nn + col0 + wc];

    const int NB = K / 16;
    for (int kb = 0; kb < NB; kb++) {
        #pragma unroll
        for (int i = 0; i < 2; i++) {
            uint32_t h0, l0, h1, l1;
            split_pair_bf16(pa[i].x, pa[i].y, h0, l0);
            split_pair_bf16(pa[i].z, pa[i].w, h1, l1);
            int r = ar + i * 64;
            Ahs[r][c2] = h0; Ahs[r][c2 + 1] = h1;
            Als[r][c2] = l0; Als[r][c2 + 1] = l1;
        }
        {
            const float* e = (const float*)&pw0;
            const float* o = (const float*)&pw1;
            #pragma unroll
            for (int j = 0; j < 4; j++) {
                uint32_t hh, ll;
                split_pair_bf16(e[j], o[j], hh, ll);
                Whs[wc + j][rp] = hh;
                Wls[wc + j][rp] = ll;
            }
        }
        __syncthreads();

        if (kb + 1 < NB) {
            int k0 = (kb + 1) * 16;
            #pragma unroll
            for (int i = 0; i < 2; i++)
                pa[i] = *(const float4*)&A[(size_t)(row0 + ar + i * 64) * K + k0 + ac];
            pw0 = *(const float4*)&W[(size_t)(k0 + 2 * rp) * Nn + col0 + wc];
            pw1 = *(const float4*)&W[(size_t)(k0 + 2 * rp + 1) * Nn + col0 + wc];
        }

        uint32_t bh0[4], bh1[4], bl0[4], bl1[4];
        #pragma unroll
        for (int fn = 0; fn < 4; fn++) {
            int col = wn * 32 + fn * 8 + g;
            bh0[fn] = Whs[col][qq];     bh1[fn] = Whs[col][qq + 4];
            bl0[fn] = Wls[col][qq];     bl1[fn] = Wls[col][qq + 4];
        }
        #pragma unroll
        for (int fm = 0; fm < 4; fm++) {
            int m = wm * 64 + fm * 16 + g;
            uint32_t ah[4], al[4];
            ah[0] = Ahs[m][qq];     ah[1] = Ahs[m + 8][qq];
            ah[2] = Ahs[m][qq + 4]; ah[3] = Ahs[m + 8][qq + 4];
            al[0] = Als[m][qq];     al[1] = Als[m + 8][qq];
            al[2] = Als[m][qq + 4]; al[3] = Als[m + 8][qq + 4];
            #pragma unroll
            for (int fn = 0; fn < 4; fn++)
                mma16(acc[fm][fn], ah[0], ah[1], ah[2], ah[3], bh0[fn], bh1[fn]);
            #pragma unroll
            for (int fn = 0; fn < 4; fn++)
                mma16(acc[fm][fn], ah[0], ah[1], ah[2], ah[3], bl0[fn], bl1[fn]);
            #pragma unroll
            for (int fn = 0; fn < 4; fn++)
                mma16(acc[fm][fn], al[0], al[1], al[2], al[3], bh0[fn], bh1[fn]);
        }
        __syncthreads();
    }

    #pragma unroll
    for (int fm = 0; fm < 4; fm++) {
        int rowA = row0 + wm * 64 + fm * 16 + g;
        #pragma unroll
        for (int fn = 0; fn < 4; fn++) {
            int col = col0 + wn * 32 + fn * 8 + 2 * qq;
            float2 p0, p1;
            p0.x = acc[fm][fn][0] + bias[col];
            p0.y = acc[fm][fn][1] + bias[col + 1];
            p1.x = acc[fm][fn][2] + bias[col];
            p1.y = acc[fm][fn][3] + bias[col + 1];
            *(float2*)&C[(size_t)rowA * Nn + col] = p0;
            *(float2*)&C[(size_t)(rowA + 8) * Nn + col] = p1;
        }
    }
}

// ============ launcher ========================================================
extern "C" void kernel_launch(void* const* d_in, const int* in_sizes, int n_in,
                              void* d_out, int out_size)
{
    const float* x  = (const float*)d_in[0];
    const float* Wq = (const float*)d_in[1];
    const float* bq = (const float*)d_in[2];
    const float* Wk = (const float*)d_in[3];
    const float* bk = (const float*)d_in[4];
    const float* Wv = (const float*)d_in[5];
    const float* bv = (const float*)d_in[6];
    const float* Wo = (const float*)d_in[7];
    const float* bo = (const float*)d_in[8];

    float* out = (float*)d_out;
    const size_t attn_elems = (size_t)B_ * H_ * N_ * N_;
    float* attn = out + ((size_t)out_size - attn_elems);

    float *q, *k, *v, *ctx;
    cudaGetSymbolAddress((void**)&q,   g_q);
    cudaGetSymbolAddress((void**)&k,   g_k);
    cudaGetSymbolAddress((void**)&v,   g_v);
    cudaGetSymbolAddress((void**)&ctx, g_ctx);

    dim3 blk(256);

    qkv_kernel<<<dim3(8, 32, 3), blk>>>(x, Wq, bq, Wk, bk, Wv, bv, q, k, v);
    scores_kernel<<<dim3(8, 8, BH), blk>>>(q, k, attn);
    entmax_kernel<<<dim3(ROWS / 8), blk>>>(attn);
    attnv_kernel<<<dim3(1, 8, BH), blk>>>(attn, v, ctx);
    proj_kernel<<<dim3(8, 32), blk>>>(ctx, Wo, bo, out);
}

// round 6
// speedup vs baseline: 2.6096x; 1.0303x over previous
#include <cuda_runtime.h>
#include <math.h>
#include <stdint.h>

#define B_  4
#define N_  1024
#define C_  1024
#define H_  16
#define DH  64
#define BH  (B_*H_)
#define ROWS (BH*N_)

// ---------------- scratch -----------------------------------------------------
__device__ float g_q[(size_t)B_*H_*N_*DH];
__device__ float g_k[(size_t)B_*H_*N_*DH];
__device__ float g_v[(size_t)B_*H_*N_*DH];
__device__ float g_ctx[(size_t)B_*N_*C_];

// ---------------- bf16 3-pass helpers -----------------------------------------
// Round-to-nearest split: hi = rn_bf16(x) (|lo| <= 2^-9 |x|), lo = rn_bf16(x-hi).
// Dropped lo*lo term + lo rounding ~ 2^-17 relative.
// Packs (even, odd) element pair: low half = even, high half = odd.
__device__ __forceinline__ void split_pair_rn(float ve, float vo,
                                              uint32_t& hi, uint32_t& lo) {
    asm("cvt.rn.bf16x2.f32 %0, %1, %2;" : "=r"(hi) : "f"(vo), "f"(ve));
    float he  = __uint_as_float(hi << 16);
    float ho  = __uint_as_float(hi & 0xFFFF0000u);
    float le  = ve - he;
    float lof = vo - ho;
    asm("cvt.rn.bf16x2.f32 %0, %1, %2;" : "=r"(lo) : "f"(lof), "f"(le));
}
__device__ __forceinline__ void mma16(float c[4],
                                      uint32_t a0, uint32_t a1, uint32_t a2, uint32_t a3,
                                      uint32_t b0, uint32_t b1) {
    asm("mma.sync.aligned.m16n8k16.row.col.f32.bf16.bf16.f32 "
        "{%0,%1,%2,%3},{%4,%5,%6,%7},{%8,%9},{%0,%1,%2,%3};"
        : "+f"(c[0]), "+f"(c[1]), "+f"(c[2]), "+f"(c[3])
        : "r"(a0), "r"(a1), "r"(a2), "r"(a3), "r"(b0), "r"(b1));
}

// ============ shared GEMM body: C = A[4096xK] @ W[KxN] + b  (3x bf16 k16) =====
// 128x128 CTA, warps 2x4 (warp tile 64x32). head_mode=1 -> [B,H,N,Dh] scatter.
__device__ __forceinline__ void gemm_bf16_body(const float* __restrict__ A,
                                               const float* __restrict__ W,
                                               const float* __restrict__ bias,
                                               float* __restrict__ C,
                                               int head_mode)
{
    __shared__ uint32_t Ahs[128][12], Als[128][12];   // [m][kpair]
    __shared__ uint32_t Whs[128][12], Wls[128][12];   // [n][kpair]

    const int K = C_, Nn = C_;
    int tid = threadIdx.x;
    int lane = tid & 31, wid = tid >> 5;
    int g = lane >> 2, qq = lane & 3;
    int wm = wid >> 2, wn = wid & 3;
    int row0 = blockIdx.y * 128;
    int col0 = blockIdx.x * 128;

    int ar = tid >> 2, ac = (tid & 3) * 4, c2 = (tid & 3) * 2;
    int rp = tid >> 5, wc = (tid & 31) * 4;

    float acc[4][4][4] = {};
    float4 pa[2], pw0, pw1;

    #pragma unroll
    for (int i = 0; i < 2; i++)
        pa[i] = *(const float4*)&A[(size_t)(row0 + ar + i * 64) * K + ac];
    pw0 = *(const float4*)&W[(size_t)(2 * rp) * Nn + col0 + wc];
    pw1 = *(const float4*)&W[(size_t)(2 * rp + 1) * Nn + col0 + wc];

    const int NB = K / 16;
    for (int kb = 0; kb < NB; kb++) {
        #pragma unroll
        for (int i = 0; i < 2; i++) {
            uint32_t h0, l0, h1, l1;
            split_pair_rn(pa[i].x, pa[i].y, h0, l0);
            split_pair_rn(pa[i].z, pa[i].w, h1, l1);
            int r = ar + i * 64;
            Ahs[r][c2] = h0; Ahs[r][c2 + 1] = h1;
            Als[r][c2] = l0; Als[r][c2 + 1] = l1;
        }
        {
            const float* e = (const float*)&pw0;
            const float* o = (const float*)&pw1;
            #pragma unroll
            for (int j = 0; j < 4; j++) {
                uint32_t hh, ll;
                split_pair_rn(e[j], o[j], hh, ll);
                Whs[wc + j][rp] = hh;
                Wls[wc + j][rp] = ll;
            }
        }
        __syncthreads();

        if (kb + 1 < NB) {
            int k0 = (kb + 1) * 16;
            #pragma unroll
            for (int i = 0; i < 2; i++)
                pa[i] = *(const float4*)&A[(size_t)(row0 + ar + i * 64) * K + k0 + ac];
            pw0 = *(const float4*)&W[(size_t)(k0 + 2 * rp) * Nn + col0 + wc];
            pw1 = *(const float4*)&W[(size_t)(k0 + 2 * rp + 1) * Nn + col0 + wc];
        }

        uint32_t bh0[4], bh1[4], bl0[4], bl1[4];
        #pragma unroll
        for (int fn = 0; fn < 4; fn++) {
            int col = wn * 32 + fn * 8 + g;
            bh0[fn] = Whs[col][qq];     bh1[fn] = Whs[col][qq + 4];
            bl0[fn] = Wls[col][qq];     bl1[fn] = Wls[col][qq + 4];
        }
        #pragma unroll
        for (int fm = 0; fm < 4; fm++) {
            int m = wm * 64 + fm * 16 + g;
            uint32_t ah[4], al[4];
            ah[0] = Ahs[m][qq];     ah[1] = Ahs[m + 8][qq];
            ah[2] = Ahs[m][qq + 4]; ah[3] = Ahs[m + 8][qq + 4];
            al[0] = Als[m][qq];     al[1] = Als[m + 8][qq];
            al[2] = Als[m][qq + 4]; al[3] = Als[m + 8][qq + 4];
            #pragma unroll
            for (int fn = 0; fn < 4; fn++)
                mma16(acc[fm][fn], ah[0], ah[1], ah[2], ah[3], bh0[fn], bh1[fn]);
            #pragma unroll
            for (int fn = 0; fn < 4; fn++)
                mma16(acc[fm][fn], ah[0], ah[1], ah[2], ah[3], bl0[fn], bl1[fn]);
            #pragma unroll
            for (int fn = 0; fn < 4; fn++)
                mma16(acc[fm][fn], al[0], al[1], al[2], al[3], bh0[fn], bh1[fn]);
        }
        __syncthreads();
    }

    #pragma unroll
    for (int fm = 0; fm < 4; fm++) {
        int rowA = row0 + wm * 64 + fm * 16 + g;
        #pragma unroll
        for (int fn = 0; fn < 4; fn++) {
            int col = col0 + wn * 32 + fn * 8 + 2 * qq;
            float2 p0, p1;
            p0.x = acc[fm][fn][0] + bias[col];
            p0.y = acc[fm][fn][1] + bias[col + 1];
            p1.x = acc[fm][fn][2] + bias[col];
            p1.y = acc[fm][fn][3] + bias[col + 1];
            if (head_mode) {
                int h = col >> 6, d = col & 63;
                int bb0 = rowA >> 10, n0 = rowA & 1023;
                int bb1 = (rowA + 8) >> 10, n1 = (rowA + 8) & 1023;
                *(float2*)&C[(((size_t)bb0 * H_ + h) * N_ + n0) * DH + d] = p0;
                *(float2*)&C[(((size_t)bb1 * H_ + h) * N_ + n1) * DH + d] = p1;
            } else {
                *(float2*)&C[(size_t)rowA * Nn + col] = p0;
                *(float2*)&C[(size_t)(rowA + 8) * Nn + col] = p1;
            }
        }
    }
}

__global__ void __launch_bounds__(256, 2)
qkv_kernel(const float* __restrict__ x,
           const float* __restrict__ Wq, const float* __restrict__ bq,
           const float* __restrict__ Wk, const float* __restrict__ bk,
           const float* __restrict__ Wv, const float* __restrict__ bv,
           float* __restrict__ q, float* __restrict__ k, float* __restrict__ v)
{
    int z = blockIdx.z;
    if (z == 0)      gemm_bf16_body(x, Wq, bq, q, 1);
    else if (z == 1) gemm_bf16_body(x, Wk, bk, k, 1);
    else             gemm_bf16_body(x, Wv, bv, v, 1);
}

__global__ void __launch_bounds__(256, 2)
proj_kernel(const float* __restrict__ A, const float* __restrict__ W,
            const float* __restrict__ bias, float* __restrict__ C)
{
    gemm_bf16_body(A, W, bias, C, 0);
}

// ============ scores: per (b,h), S = Q @ K^T * 0.125 (3x bf16 k16) ============
// 128x128 CTA, warps 2x4; K=64 in two 32-deep smem phases (96 mmas/barrier).
__global__ void __launch_bounds__(256, 2)
scores_kernel(const float* __restrict__ Q, const float* __restrict__ Km,
              float* __restrict__ S)
{
    __shared__ uint32_t Qp[128][20], Ql[128][20];   // [m][kpair], stride 20
    __shared__ uint32_t Kp[128][20], Kl[128][20];   // [n][kpair]

    int z = blockIdx.z;
    const float* Qb = Q  + (size_t)z * N_ * DH;
    const float* Kb = Km + (size_t)z * N_ * DH;

    int tid = threadIdx.x;
    int lane = tid & 31, wid = tid >> 5;
    int g = lane >> 2, qq = lane & 3;
    int wm = wid >> 2, wn = wid & 3;
    int row0 = blockIdx.y * 128;
    int col0 = blockIdx.x * 128;

    int r = tid >> 1;
    int cbase = (tid & 1) * 4;     // float4-chunk base within 32-float k-block

    float acc[4][4][4] = {};

    #pragma unroll
    for (int kb = 0; kb < 2; kb++) {
        int k0 = kb * 32;
        #pragma unroll
        for (int j = 0; j < 4; j++) {
            int c = cbase + j;                         // chunk 0..7
            float4 vq = *(const float4*)&Qb[(size_t)(row0 + r) * DH + k0 + c * 4];
            float4 vk = *(const float4*)&Kb[(size_t)(col0 + r) * DH + k0 + c * 4];
            uint32_t h0, l0, h1, l1;
            split_pair_rn(vq.x, vq.y, h0, l0);
            split_pair_rn(vq.z, vq.w, h1, l1);
            Qp[r][c * 2] = h0; Qp[r][c * 2 + 1] = h1;
            Ql[r][c * 2] = l0; Ql[r][c * 2 + 1] = l1;
            split_pair_rn(vk.x, vk.y, h0, l0);
            split_pair_rn(vk.z, vk.w, h1, l1);
            Kp[r][c * 2] = h0; Kp[r][c * 2 + 1] = h1;
            Kl[r][c * 2] = l0; Kl[r][c * 2 + 1] = l1;
        }
        __syncthreads();

        #pragma unroll
        for (int ks = 0; ks < 2; ks++) {
            int pb = ks * 8;
            uint32_t bh0[4], bh1[4], bl0[4], bl1[4];
            #pragma unroll
            for (int fn = 0; fn < 4; fn++) {
                int col = wn * 32 + fn * 8 + g;
                bh0[fn] = Kp[col][pb + qq];     bh1[fn] = Kp[col][pb + qq + 4];
                bl0[fn] = Kl[col][pb + qq];     bl1[fn] = Kl[col][pb + qq + 4];
            }
            #pragma unroll
            for (int fm = 0; fm < 4; fm++) {
                int m = wm * 64 + fm * 16 + g;
                uint32_t ah[4], al[4];
                ah[0] = Qp[m][pb + qq];     ah[1] = Qp[m + 8][pb + qq];
                ah[2] = Qp[m][pb + qq + 4]; ah[3] = Qp[m + 8][pb + qq + 4];
                al[0] = Ql[m][pb + qq];     al[1] = Ql[m + 8][pb + qq];
                al[2] = Ql[m][pb + qq + 4]; al[3] = Ql[m + 8][pb + qq + 4];
                #pragma unroll
                for (int fn = 0; fn < 4; fn++)
                    mma16(acc[fm][fn], ah[0], ah[1], ah[2], ah[3], bh0[fn], bh1[fn]);
                #pragma unroll
                for (int fn = 0; fn < 4; fn++)
                    mma16(acc[fm][fn], ah[0], ah[1], ah[2], ah[3], bl0[fn], bl1[fn]);
                #pragma unroll
                for (int fn = 0; fn < 4; fn++)
                    mma16(acc[fm][fn], al[0], al[1], al[2], al[3], bh0[fn], bh1[fn]);
            }
        }
        if (kb == 0) __syncthreads();
    }

    float* Sb = S + (size_t)z * N_ * N_;
    #pragma unroll
    for (int fm = 0; fm < 4; fm++) {
        int rowA = row0 + wm * 64 + fm * 16 + g;
        #pragma unroll
        for (int fn = 0; fn < 4; fn++) {
            int col = col0 + wn * 32 + fn * 8 + 2 * qq;
            float2 p0, p1;
            p0.x = acc[fm][fn][0] * 0.125f;
            p0.y = acc[fm][fn][1] * 0.125f;
            p1.x = acc[fm][fn][2] * 0.125f;
            p1.y = acc[fm][fn][3] * 0.125f;
            *(float2*)&Sb[(size_t)rowA * N_ + col] = p0;
            *(float2*)&Sb[(size_t)(rowA + 8) * N_ + col] = p1;
        }
    }
}

// ============ entmax: 14 bisection iters + exact quadratic finish =============
__global__ void entmax_kernel(float* __restrict__ attn)
{
    int warp = threadIdx.x >> 5;
    int lane = threadIdx.x & 31;
    size_t row = (size_t)blockIdx.x * 8 + warp;
    float* S = attn + row * N_;

    float xa[32];
    float mx = -INFINITY;
    #pragma unroll
    for (int i = 0; i < 32; i++) {
        float v = S[i * 32 + lane] * 0.5f;
        xa[i] = v;
        mx = fmaxf(mx, v);
    }
    #pragma unroll
    for (int o = 16; o; o >>= 1)
        mx = fmaxf(mx, __shfl_xor_sync(0xFFFFFFFFu, mx, o));

    float tau_lo = mx - 1.0f;
    float dm = 1.0f - 0.03125f;

    float f_lo = 0.0f;
    #pragma unroll
    for (int i = 0; i < 32; i++) {
        float t = fmaxf(xa[i] - tau_lo, 0.0f);
        f_lo = fmaf(t, t, f_lo);
    }
    #pragma unroll
    for (int o = 16; o; o >>= 1)
        f_lo += __shfl_xor_sync(0xFFFFFFFFu, f_lo, o);
    f_lo -= 1.0f;

    for (int it = 0; it < 14; it++) {
        dm *= 0.5f;
        float tau_m = tau_lo + dm;
        float f = 0.0f;
        #pragma unroll
        for (int i = 0; i < 32; i++) {
            float t = fmaxf(xa[i] - tau_m, 0.0f);
            f = fmaf(t, t, f);
        }
        #pragma unroll
        for (int o = 16; o; o >>= 1)
            f += __shfl_xor_sync(0xFFFFFFFFu, f, o);
        f -= 1.0f;
        if (f * f_lo >= 0.0f) tau_lo = tau_m;
    }

    int   cnt = 0;
    float S1 = 0.0f, S2 = 0.0f;
    #pragma unroll
    for (int i = 0; i < 32; i++) {
        if (xa[i] > tau_lo) {
            cnt += 1;
            S1 += xa[i];
            S2 = fmaf(xa[i], xa[i], S2);
        }
    }
    #pragma unroll
    for (int o = 16; o; o >>= 1) {
        cnt += __shfl_xor_sync(0xFFFFFFFFu, cnt, o);
        S1  += __shfl_xor_sync(0xFFFFFFFFu, S1, o);
        S2  += __shfl_xor_sync(0xFFFFFFFFu, S2, o);
    }
    float kf = (float)cnt;
    float disc = fmaxf(fmaf(S1, S1, -kf * (S2 - 1.0f)), 0.0f);
    float tau = (S1 - sqrtf(disc)) / kf;
    tau = fminf(fmaxf(tau, tau_lo), tau_lo + dm);

    float p[32];
    float s = 0.0f;
    #pragma unroll
    for (int i = 0; i < 32; i++) {
        float t = fmaxf(xa[i] - tau, 0.0f);
        p[i] = t * t;
        s += p[i];
    }
    #pragma unroll
    for (int o = 16; o; o >>= 1)
        s += __shfl_xor_sync(0xFFFFFFFFu, s, o);
    float inv = 1.0f / s;

    #pragma unroll
    for (int i = 0; i < 32; i++)
        S[i * 32 + lane] = p[i] * inv;
}

// ============ ctx = attn @ V per (b,h): 3x bf16 m16n8k16 ======================
__global__ void __launch_bounds__(256, 2)
attnv_kernel(const float* __restrict__ Attn, const float* __restrict__ V,
             float* __restrict__ ctx)
{
    __shared__ uint32_t Ahs[128][12], Als[128][12];   // [m][kpair]
    __shared__ uint32_t Vhs[64][12],  Vls[64][12];    // [d][kpair]

    int z = blockIdx.z;
    int bb = z >> 4, h = z & 15;
    const float* Ab = Attn + (size_t)z * N_ * N_;
    const float* Vb = V    + (size_t)z * N_ * DH;

    int tid = threadIdx.x;
    int lane = tid & 31, wid = tid >> 5;
    int g = lane >> 2, qq = lane & 3;
    int wm = wid >> 1, wn = wid & 1;
    int row0 = blockIdx.y * 128;

    int ar = tid >> 2, ac = (tid & 3) * 4, c2 = (tid & 3) * 2;
    int rp = (tid & 127) >> 4, vc = (tid & 15) * 4;
    bool vload = tid < 128;

    float acc[2][4][4] = {};
    float4 pa[2], pv0, pv1;

    #pragma unroll
    for (int i = 0; i < 2; i++)
        pa[i] = *(const float4*)&Ab[(size_t)(row0 + ar + i * 64) * N_ + ac];
    if (vload) {
        pv0 = *(const float4*)&Vb[(size_t)(2 * rp) * DH + vc];
        pv1 = *(const float4*)&Vb[(size_t)(2 * rp + 1) * DH + vc];
    }

    const int NB = N_ / 16;
    for (int kb = 0; kb < NB; kb++) {
        #pragma unroll
        for (int i = 0; i < 2; i++) {
            uint32_t h0, l0, h1, l1;
            split_pair_rn(pa[i].x, pa[i].y, h0, l0);
            split_pair_rn(pa[i].z, pa[i].w, h1, l1);
            int r = ar + i * 64;
            Ahs[r][c2] = h0; Ahs[r][c2 + 1] = h1;
            Als[r][c2] = l0; Als[r][c2 + 1] = l1;
        }
        if (vload) {
            const float* e = (const float*)&pv0;
            const float* o = (const float*)&pv1;
            #pragma unroll
            for (int j = 0; j < 4; j++) {
                uint32_t hh, ll;
                split_pair_rn(e[j], o[j], hh, ll);
                Vhs[vc + j][rp] = hh;
                Vls[vc + j][rp] = ll;
            }
        }
        __syncthreads();

        if (kb + 1 < NB) {
            int k0 = (kb + 1) * 16;
            #pragma unroll
            for (int i = 0; i < 2; i++)
                pa[i] = *(const float4*)&Ab[(size_t)(row0 + ar + i * 64) * N_ + k0 + ac];
            if (vload) {
                pv0 = *(const float4*)&Vb[(size_t)(k0 + 2 * rp) * DH + vc];
                pv1 = *(const float4*)&Vb[(size_t)(k0 + 2 * rp + 1) * DH + vc];
            }
        }

        uint32_t bh0[4], bh1[4], bl0[4], bl1[4];
        #pragma unroll
        for (int fn = 0; fn < 4; fn++) {
            int col = wn * 32 + fn * 8 + g;
            bh0[fn] = Vhs[col][qq];     bh1[fn] = Vhs[col][qq + 4];
            bl0[fn] = Vls[col][qq];     bl1[fn] = Vls[col][qq + 4];
        }
        #pragma unroll
        for (int fm = 0; fm < 2; fm++) {
            int m = wm * 32 + fm * 16 + g;
            uint32_t ah[4], al[4];
            ah[0] = Ahs[m][qq];     ah[1] = Ahs[m + 8][qq];
            ah[2] = Ahs[m][qq + 4]; ah[3] = Ahs[m + 8][qq + 4];
            al[0] = Als[m][qq];     al[1] = Als[m + 8][qq];
            al[2] = Als[m][qq + 4]; al[3] = Als[m + 8][qq + 4];
            #pragma unroll
            for (int fn = 0; fn < 4; fn++)
                mma16(acc[fm][fn], ah[0], ah[1], ah[2], ah[3], bh0[fn], bh1[fn]);
            #pragma unroll
            for (int fn = 0; fn < 4; fn++)
                mma16(acc[fm][fn], ah[0], ah[1], ah[2], ah[3], bl0[fn], bl1[fn]);
            #pragma unroll
            for (int fn = 0; fn < 4; fn++)
                mma16(acc[fm][fn], al[0], al[1], al[2], al[3], bh0[fn], bh1[fn]);
        }
        __syncthreads();
    }

    #pragma unroll
    for (int fm = 0; fm < 2; fm++) {
        int n = row0 + wm * 32 + fm * 16 + g;
        #pragma unroll
        for (int fn = 0; fn < 4; fn++) {
            int d = wn * 32 + fn * 8 + 2 * qq;
            float2 p0, p1;
            p0.x = acc[fm][fn][0]; p0.y = acc[fm][fn][1];
            p1.x = acc[fm][fn][2]; p1.y = acc[fm][fn][3];
            *(float2*)&ctx[((size_t)bb * N_ + n) * C_ + h * DH + d] = p0;
            *(float2*)&ctx[((size_t)bb * N_ + n + 8) * C_ + h * DH + d] = p1;
        }
    }
}

// ============ launcher ========================================================
extern "C" void kernel_launch(void* const* d_in, const int* in_sizes, int n_in,
                              void* d_out, int out_size)
{
    const float* x  = (const float*)d_in[0];
    const float* Wq = (const float*)d_in[1];
    const float* bq = (const float*)d_in[2];
    const float* Wk = (const float*)d_in[3];
    const float* bk = (const float*)d_in[4];
    const float* Wv = (const float*)d_in[5];
    const float* bv = (const float*)d_in[6];
    const float* Wo = (const float*)d_in[7];
    const float* bo = (const float*)d_in[8];

    float* out = (float*)d_out;
    const size_t attn_elems = (size_t)B_ * H_ * N_ * N_;
    float* attn = out + ((size_t)out_size - attn_elems);

    float *q, *k, *v, *ctx;
    cudaGetSymbolAddress((void**)&q,   g_q);
    cudaGetSymbolAddress((void**)&k,   g_k);
    cudaGetSymbolAddress((void**)&v,   g_v);
    cudaGetSymbolAddress((void**)&ctx, g_ctx);

    dim3 blk(256);

    qkv_kernel<<<dim3(8, 32, 3), blk>>>(x, Wq, bq, Wk, bk, Wv, bv, q, k, v);
    scores_kernel<<<dim3(8, 8, BH), blk>>>(q, k, attn);
    entmax_kernel<<<dim3(ROWS / 8), blk>>>(attn);
    attnv_kernel<<<dim3(1, 8, BH), blk>>>(attn, v, ctx);
    proj_kernel<<<dim3(8, 32), blk>>>(ctx, Wo, bo, out);
}

// round 9
// speedup vs baseline: 2.6828x; 1.0281x over previous
#include <cuda_runtime.h>
#include <math.h>
#include <stdint.h>

#define B_  4
#define N_  1024
#define C_  1024
#define H_  16
#define DH  64
#define BH  (B_*H_)
#define ROWS (BH*N_)

// ---------------- scratch -----------------------------------------------------
__device__ float g_q[(size_t)B_*H_*N_*DH];
__device__ float g_k[(size_t)B_*H_*N_*DH];
__device__ float g_v[(size_t)B_*H_*N_*DH];
__device__ float g_ctx[(size_t)B_*N_*C_];

// ---------------- bf16 3-pass helpers -----------------------------------------
__device__ __forceinline__ void split_pair_rn(float ve, float vo,
                                              uint32_t& hi, uint32_t& lo) {
    asm("cvt.rn.bf16x2.f32 %0, %1, %2;" : "=r"(hi) : "f"(vo), "f"(ve));
    float he  = __uint_as_float(hi << 16);
    float ho  = __uint_as_float(hi & 0xFFFF0000u);
    float le  = ve - he;
    float lof = vo - ho;
    asm("cvt.rn.bf16x2.f32 %0, %1, %2;" : "=r"(lo) : "f"(lof), "f"(le));
}
__device__ __forceinline__ void mma16(float c[4],
                                      uint32_t a0, uint32_t a1, uint32_t a2, uint32_t a3,
                                      uint32_t b0, uint32_t b1) {
    asm("mma.sync.aligned.m16n8k16.row.col.f32.bf16.bf16.f32 "
        "{%0,%1,%2,%3},{%4,%5,%6,%7},{%8,%9},{%0,%1,%2,%3};"
        : "+f"(c[0]), "+f"(c[1]), "+f"(c[2]), "+f"(c[3])
        : "r"(a0), "r"(a1), "r"(a2), "r"(a3), "r"(b0), "r"(b1));
}

// ============ GEMM: C[4096x1024] = A @ W + b (3x bf16 k16), pipelined =========
// 128x128 CTA, warps 2x4 (warp tile 64x32). Double-buffered smem; HMMA issued
// first each iteration so tensor work overlaps the next block's split/store.
__device__ __forceinline__ void gemm_bf16_body(const float* __restrict__ A,
                                               const float* __restrict__ W,
                                               const float* __restrict__ bias,
                                               float* __restrict__ C,
                                               int head_mode)
{
    __shared__ uint32_t Ahs[2][128][12], Als[2][128][12];   // [buf][m][kpair]
    __shared__ uint32_t Whs[2][128][12], Wls[2][128][12];   // [buf][n][kpair]

    const int K = C_, Nn = C_;
    int tid = threadIdx.x;
    int lane = tid & 31, wid = tid >> 5;
    int g = lane >> 2, qq = lane & 3;
    int wm = wid >> 2, wn = wid & 3;
    int row0 = blockIdx.y * 128;
    int col0 = blockIdx.x * 128;

    int ar = tid >> 2, ac = (tid & 3) * 4, c2 = (tid & 3) * 2;
    int rp = tid >> 5, wc = (tid & 31) * 4;

    float acc[4][4][4] = {};
    float4 pa[2], pw0, pw1;

    // ---- prologue: load + split + store block 0, prefetch block 1 ----
    #pragma unroll
    for (int i = 0; i < 2; i++)
        pa[i] = *(const float4*)&A[(size_t)(row0 + ar + i * 64) * K + ac];
    pw0 = *(const float4*)&W[(size_t)(2 * rp) * Nn + col0 + wc];
    pw1 = *(const float4*)&W[(size_t)(2 * rp + 1) * Nn + col0 + wc];

    #pragma unroll
    for (int i = 0; i < 2; i++) {
        uint32_t h0, l0, h1, l1;
        split_pair_rn(pa[i].x, pa[i].y, h0, l0);
        split_pair_rn(pa[i].z, pa[i].w, h1, l1);
        int r = ar + i * 64;
        Ahs[0][r][c2] = h0; Ahs[0][r][c2 + 1] = h1;
        Als[0][r][c2] = l0; Als[0][r][c2 + 1] = l1;
    }
    {
        const float* e = (const float*)&pw0;
        const float* o = (const float*)&pw1;
        #pragma unroll
        for (int j = 0; j < 4; j++) {
            uint32_t hh, ll;
            split_pair_rn(e[j], o[j], hh, ll);
            Whs[0][wc + j][rp] = hh;
            Wls[0][wc + j][rp] = ll;
        }
    }
    // prefetch block 1
    #pragma unroll
    for (int i = 0; i < 2; i++)
        pa[i] = *(const float4*)&A[(size_t)(row0 + ar + i * 64) * K + 16 + ac];
    pw0 = *(const float4*)&W[(size_t)(16 + 2 * rp) * Nn + col0 + wc];
    pw1 = *(const float4*)&W[(size_t)(16 + 2 * rp + 1) * Nn + col0 + wc];
    __syncthreads();

    const int NB = K / 16;
    for (int kb = 0; kb < NB; kb++) {
        int cur = kb & 1;

        // ---- mma phase: fragments from buf[cur], HMMA issued first ----
        uint32_t bh0[4], bh1[4], bl0[4], bl1[4];
        #pragma unroll
        for (int fn = 0; fn < 4; fn++) {
            int col = wn * 32 + fn * 8 + g;
            bh0[fn] = Whs[cur][col][qq];     bh1[fn] = Whs[cur][col][qq + 4];
            bl0[fn] = Wls[cur][col][qq];     bl1[fn] = Wls[cur][col][qq + 4];
        }
        #pragma unroll
        for (int fm = 0; fm < 4; fm++) {
            int m = wm * 64 + fm * 16 + g;
            uint32_t ah[4], al[4];
            ah[0] = Ahs[cur][m][qq];     ah[1] = Ahs[cur][m + 8][qq];
            ah[2] = Ahs[cur][m][qq + 4]; ah[3] = Ahs[cur][m + 8][qq + 4];
            al[0] = Als[cur][m][qq];     al[1] = Als[cur][m + 8][qq];
            al[2] = Als[cur][m][qq + 4]; al[3] = Als[cur][m + 8][qq + 4];
            #pragma unroll
            for (int fn = 0; fn < 4; fn++)
                mma16(acc[fm][fn], ah[0], ah[1], ah[2], ah[3], bh0[fn], bh1[fn]);
            #pragma unroll
            for (int fn = 0; fn < 4; fn++)
                mma16(acc[fm][fn], ah[0], ah[1], ah[2], ah[3], bl0[fn], bl1[fn]);
            #pragma unroll
            for (int fn = 0; fn < 4; fn++)
                mma16(acc[fm][fn], al[0], al[1], al[2], al[3], bh0[fn], bh1[fn]);
        }

        // ---- store phase: split block kb+1 into buf[cur^1] (overlaps HMMA) --
        if (kb + 1 < NB) {
            int nxt = cur ^ 1;
            #pragma unroll
            for (int i = 0; i < 2; i++) {
                uint32_t h0, l0, h1, l1;
                split_pair_rn(pa[i].x, pa[i].y, h0, l0);
                split_pair_rn(pa[i].z, pa[i].w, h1, l1);
                int r = ar + i * 64;
                Ahs[nxt][r][c2] = h0; Ahs[nxt][r][c2 + 1] = h1;
                Als[nxt][r][c2] = l0; Als[nxt][r][c2 + 1] = l1;
            }
            {
                const float* e = (const float*)&pw0;
                const float* o = (const float*)&pw1;
                #pragma unroll
                for (int j = 0; j < 4; j++) {
                    uint32_t hh, ll;
                    split_pair_rn(e[j], o[j], hh, ll);
                    Whs[nxt][wc + j][rp] = hh;
                    Wls[nxt][wc + j][rp] = ll;
                }
            }
            if (kb + 2 < NB) {
                int k0 = (kb + 2) * 16;
                #pragma unroll
                for (int i = 0; i < 2; i++)
                    pa[i] = *(const float4*)&A[(size_t)(row0 + ar + i * 64) * K + k0 + ac];
                pw0 = *(const float4*)&W[(size_t)(k0 + 2 * rp) * Nn + col0 + wc];
                pw1 = *(const float4*)&W[(size_t)(k0 + 2 * rp + 1) * Nn + col0 + wc];
            }
        }
        __syncthreads();
    }

    #pragma unroll
    for (int fm = 0; fm < 4; fm++) {
        int rowA = row0 + wm * 64 + fm * 16 + g;
        #pragma unroll
        for (int fn = 0; fn < 4; fn++) {
            int col = col0 + wn * 32 + fn * 8 + 2 * qq;
            float2 p0, p1;
            p0.x = acc[fm][fn][0] + bias[col];
            p0.y = acc[fm][fn][1] + bias[col + 1];
            p1.x = acc[fm][fn][2] + bias[col];
            p1.y = acc[fm][fn][3] + bias[col + 1];
            if (head_mode) {
                int h = col >> 6, d = col & 63;
                int bb0 = rowA >> 10, n0 = rowA & 1023;
                int bb1 = (rowA + 8) >> 10, n1 = (rowA + 8) & 1023;
                *(float2*)&C[(((size_t)bb0 * H_ + h) * N_ + n0) * DH + d] = p0;
                *(float2*)&C[(((size_t)bb1 * H_ + h) * N_ + n1) * DH + d] = p1;
            } else {
                *(float2*)&C[(size_t)rowA * Nn + col] = p0;
                *(float2*)&C[(size_t)(rowA + 8) * Nn + col] = p1;
            }
        }
    }
}

__global__ void __launch_bounds__(256, 2)
qkv_kernel(const float* __restrict__ x,
           const float* __restrict__ Wq, const float* __restrict__ bq,
           const float* __restrict__ Wk, const float* __restrict__ bk,
           const float* __restrict__ Wv, const float* __restrict__ bv,
           float* __restrict__ q, float* __restrict__ k, float* __restrict__ v)
{
    int z = blockIdx.z;
    if (z == 0)      gemm_bf16_body(x, Wq, bq, q, 1);
    else if (z == 1) gemm_bf16_body(x, Wk, bk, k, 1);
    else             gemm_bf16_body(x, Wv, bv, v, 1);
}

__global__ void __launch_bounds__(256, 2)
proj_kernel(const float* __restrict__ A, const float* __restrict__ W,
            const float* __restrict__ bias, float* __restrict__ C)
{
    gemm_bf16_body(A, W, bias, C, 0);
}

// ============ scores: per (b,h), S = Q @ K^T * 0.125 (3x bf16 k16) ============
__global__ void __launch_bounds__(256, 2)
scores_kernel(const float* __restrict__ Q, const float* __restrict__ Km,
              float* __restrict__ S)
{
    __shared__ uint32_t Qp[128][20], Ql[128][20];
    __shared__ uint32_t Kp[128][20], Kl[128][20];

    int z = blockIdx.z;
    const float* Qb = Q  + (size_t)z * N_ * DH;
    const float* Kb = Km + (size_t)z * N_ * DH;

    int tid = threadIdx.x;
    int lane = tid & 31, wid = tid >> 5;
    int g = lane >> 2, qq = lane & 3;
    int wm = wid >> 2, wn = wid & 3;
    int row0 = blockIdx.y * 128;
    int col0 = blockIdx.x * 128;

    int r = tid >> 1;
    int cbase = (tid & 1) * 4;

    float acc[4][4][4] = {};

    #pragma unroll
    for (int kb = 0; kb < 2; kb++) {
        int k0 = kb * 32;
        #pragma unroll
        for (int j = 0; j < 4; j++) {
            int c = cbase + j;
            float4 vq = *(const float4*)&Qb[(size_t)(row0 + r) * DH + k0 + c * 4];
            float4 vk = *(const float4*)&Kb[(size_t)(col0 + r) * DH + k0 + c * 4];
            uint32_t h0, l0, h1, l1;
            split_pair_rn(vq.x, vq.y, h0, l0);
            split_pair_rn(vq.z, vq.w, h1, l1);
            Qp[r][c * 2] = h0; Qp[r][c * 2 + 1] = h1;
            Ql[r][c * 2] = l0; Ql[r][c * 2 + 1] = l1;
            split_pair_rn(vk.x, vk.y, h0, l0);
            split_pair_rn(vk.z, vk.w, h1, l1);
            Kp[r][c * 2] = h0; Kp[r][c * 2 + 1] = h1;
            Kl[r][c * 2] = l0; Kl[r][c * 2 + 1] = l1;
        }
        __syncthreads();

        #pragma unroll
        for (int ks = 0; ks < 2; ks++) {
            int pb = ks * 8;
            uint32_t bh0[4], bh1[4], bl0[4], bl1[4];
            #pragma unroll
            for (int fn = 0; fn < 4; fn++) {
                int col = wn * 32 + fn * 8 + g;
                bh0[fn] = Kp[col][pb + qq];     bh1[fn] = Kp[col][pb + qq + 4];
                bl0[fn] = Kl[col][pb + qq];     bl1[fn] = Kl[col][pb + qq + 4];
            }
            #pragma unroll
            for (int fm = 0; fm < 4; fm++) {
                int m = wm * 64 + fm * 16 + g;
                uint32_t ah[4], al[4];
                ah[0] = Qp[m][pb + qq];     ah[1] = Qp[m + 8][pb + qq];
                ah[2] = Qp[m][pb + qq + 4]; ah[3] = Qp[m + 8][pb + qq + 4];
                al[0] = Ql[m][pb + qq];     al[1] = Ql[m + 8][pb + qq];
                al[2] = Ql[m][pb + qq + 4]; al[3] = Ql[m + 8][pb + qq + 4];
                #pragma unroll
                for (int fn = 0; fn < 4; fn++)
                    mma16(acc[fm][fn], ah[0], ah[1], ah[2], ah[3], bh0[fn], bh1[fn]);
                #pragma unroll
                for (int fn = 0; fn < 4; fn++)
                    mma16(acc[fm][fn], ah[0], ah[1], ah[2], ah[3], bl0[fn], bl1[fn]);
                #pragma unroll
                for (int fn = 0; fn < 4; fn++)
                    mma16(acc[fm][fn], al[0], al[1], al[2], al[3], bh0[fn], bh1[fn]);
            }
        }
        if (kb == 0) __syncthreads();
    }

    float* Sb = S + (size_t)z * N_ * N_;
    #pragma unroll
    for (int fm = 0; fm < 4; fm++) {
        int rowA = row0 + wm * 64 + fm * 16 + g;
        #pragma unroll
        for (int fn = 0; fn < 4; fn++) {
            int col = col0 + wn * 32 + fn * 8 + 2 * qq;
            float2 p0, p1;
            p0.x = acc[fm][fn][0] * 0.125f;
            p0.y = acc[fm][fn][1] * 0.125f;
            p1.x = acc[fm][fn][2] * 0.125f;
            p1.y = acc[fm][fn][3] * 0.125f;
            *(float2*)&Sb[(size_t)rowA * N_ + col] = p0;
            *(float2*)&Sb[(size_t)(rowA + 8) * N_ + col] = p1;
        }
    }
}

// ============ entmax: 10 bisection iters + exact quadratic finish =============
__global__ void entmax_kernel(float* __restrict__ attn)
{
    int warp = threadIdx.x >> 5;
    int lane = threadIdx.x & 31;
    size_t row = (size_t)blockIdx.x * 8 + warp;
    float* S = attn + row * N_;

    float xa[32];
    float mx = -INFINITY;
    #pragma unroll
    for (int i = 0; i < 32; i++) {
        float v = S[i * 32 + lane] * 0.5f;
        xa[i] = v;
        mx = fmaxf(mx, v);
    }
    #pragma unroll
    for (int o = 16; o; o >>= 1)
        mx = fmaxf(mx, __shfl_xor_sync(0xFFFFFFFFu, mx, o));

    float tau_lo = mx - 1.0f;
    float dm = 1.0f - 0.03125f;

    float f_lo = 0.0f;
    #pragma unroll
    for (int i = 0; i < 32; i++) {
        float t = fmaxf(xa[i] - tau_lo, 0.0f);
        f_lo = fmaf(t, t, f_lo);
    }
    #pragma unroll
    for (int o = 16; o; o >>= 1)
        f_lo += __shfl_xor_sync(0xFFFFFFFFu, f_lo, o);
    f_lo -= 1.0f;

    for (int it = 0; it < 10; it++) {
        dm *= 0.5f;
        float tau_m = tau_lo + dm;
        float f = 0.0f;
        #pragma unroll
        for (int i = 0; i < 32; i++) {
            float t = fmaxf(xa[i] - tau_m, 0.0f);
            f = fmaf(t, t, f);
        }
        #pragma unroll
        for (int o = 16; o; o >>= 1)
            f += __shfl_xor_sync(0xFFFFFFFFu, f, o);
        f -= 1.0f;
        if (f * f_lo >= 0.0f) tau_lo = tau_m;
    }

    int   cnt = 0;
    float S1 = 0.0f, S2 = 0.0f;
    #pragma unroll
    for (int i = 0; i < 32; i++) {
        if (xa[i] > tau_lo) {
            cnt += 1;
            S1 += xa[i];
            S2 = fmaf(xa[i], xa[i], S2);
        }
    }
    #pragma unroll
    for (int o = 16; o; o >>= 1) {
        cnt += __shfl_xor_sync(0xFFFFFFFFu, cnt, o);
        S1  += __shfl_xor_sync(0xFFFFFFFFu, S1, o);
        S2  += __shfl_xor_sync(0xFFFFFFFFu, S2, o);
    }
    float kf = (float)cnt;
    float disc = fmaxf(fmaf(S1, S1, -kf * (S2 - 1.0f)), 0.0f);
    float tau = (S1 - sqrtf(disc)) / kf;
    tau = fminf(fmaxf(tau, tau_lo), tau_lo + dm);

    float p[32];
    float s = 0.0f;
    #pragma unroll
    for (int i = 0; i < 32; i++) {
        float t = fmaxf(xa[i] - tau, 0.0f);
        p[i] = t * t;
        s += p[i];
    }
    #pragma unroll
    for (int o = 16; o; o >>= 1)
        s += __shfl_xor_sync(0xFFFFFFFFu, s, o);
    float inv = 1.0f / s;

    #pragma unroll
    for (int i = 0; i < 32; i++)
        S[i * 32 + lane] = p[i] * inv;
}

// ============ ctx = attn @ V per (b,h): 3x bf16 k16, pipelined ================
__global__ void __launch_bounds__(256, 2)
attnv_kernel(const float* __restrict__ Attn, const float* __restrict__ V,
             float* __restrict__ ctx)
{
    __shared__ uint32_t Ahs[2][128][12], Als[2][128][12];   // [buf][m][kpair]
    __shared__ uint32_t Vhs[2][64][12],  Vls[2][64][12];    // [buf][d][kpair]

    int z = blockIdx.z;
    int bb = z >> 4, h = z & 15;
    const float* Ab = Attn + (size_t)z * N_ * N_;
    const float* Vb = V    + (size_t)z * N_ * DH;

    int tid = threadIdx.x;
    int lane = tid & 31, wid = tid >> 5;
    int g = lane >> 2, qq = lane & 3;
    int wm = wid >> 1, wn = wid & 1;
    int row0 = blockIdx.y * 128;

    int ar = tid >> 2, ac = (tid & 3) * 4, c2 = (tid & 3) * 2;
    int rp = (tid & 127) >> 4, vc = (tid & 15) * 4;
    bool vload = tid < 128;

    float acc[2][4][4] = {};
    float4 pa[2], pv0, pv1;

    // ---- prologue: block 0 ----
    #pragma unroll
    for (int i = 0; i < 2; i++)
        pa[i] = *(const float4*)&Ab[(size_t)(row0 + ar + i * 64) * N_ + ac];
    if (vload) {
        pv0 = *(const float4*)&Vb[(size_t)(2 * rp) * DH + vc];
        pv1 = *(const float4*)&Vb[(size_t)(2 * rp + 1) * DH + vc];
    }
    #pragma unroll
    for (int i = 0; i < 2; i++) {
        uint32_t h0, l0, h1, l1;
        split_pair_rn(pa[i].x, pa[i].y, h0, l0);
        split_pair_rn(pa[i].z, pa[i].w, h1, l1);
        int r = ar + i * 64;
        Ahs[0][r][c2] = h0; Ahs[0][r][c2 + 1] = h1;
        Als[0][r][c2] = l0; Als[0][r][c2 + 1] = l1;
    }
    if (vload) {
        const float* e = (const float*)&pv0;
        const float* o = (const float*)&pv1;
        #pragma unroll
        for (int j = 0; j < 4; j++) {
            uint32_t hh, ll;
            split_pair_rn(e[j], o[j], hh, ll);
            Vhs[0][vc + j][rp] = hh;
            Vls[0][vc + j][rp] = ll;
        }
    }
    #pragma unroll
    for (int i = 0; i < 2; i++)
        pa[i] = *(const float4*)&Ab[(size_t)(row0 + ar + i * 64) * N_ + 16 + ac];
    if (vload) {
        pv0 = *(const float4*)&Vb[(size_t)(16 + 2 * rp) * DH + vc];
        pv1 = *(const float4*)&Vb[(size_t)(16 + 2 * rp + 1) * DH + vc];
    }
    __syncthreads();

    const int NB = N_ / 16;
    for (int kb = 0; kb < NB; kb++) {
        int cur = kb & 1;

        // ---- mma phase on buf[cur] ----
        uint32_t bh0[4], bh1[4], bl0[4], bl1[4];
        #pragma unroll
        for (int fn = 0; fn < 4; fn++) {
            int col = wn * 32 + fn * 8 + g;
            bh0[fn] = Vhs[cur][col][qq];     bh1[fn] = Vhs[cur][col][qq + 4];
            bl0[fn] = Vls[cur][col][qq];     bl1[fn] = Vls[cur][col][qq + 4];
        }
        #pragma unroll
        for (int fm = 0; fm < 2; fm++) {
            int m = wm * 32 + fm * 16 + g;
            uint32_t ah[4], al[4];
            ah[0] = Ahs[cur][m][qq];     ah[1] = Ahs[cur][m + 8][qq];
            ah[2] = Ahs[cur][m][qq + 4]; ah[3] = Ahs[cur][m + 8][qq + 4];
            al[0] = Als[cur][m][qq];     al[1] = Als[cur][m + 8][qq];
            al[2] = Als[cur][m][qq + 4]; al[3] = Als[cur][m + 8][qq + 4];
            #pragma unroll
            for (int fn = 0; fn < 4; fn++)
                mma16(acc[fm][fn], ah[0], ah[1], ah[2], ah[3], bh0[fn], bh1[fn]);
            #pragma unroll
            for (int fn = 0; fn < 4; fn++)
                mma16(acc[fm][fn], ah[0], ah[1], ah[2], ah[3], bl0[fn], bl1[fn]);
            #pragma unroll
            for (int fn = 0; fn < 4; fn++)
                mma16(acc[fm][fn], al[0], al[1], al[2], al[3], bh0[fn], bh1[fn]);
        }

        // ---- store phase: split block kb+1 into buf[cur^1] ----
        if (kb + 1 < NB) {
            int nxt = cur ^ 1;
            #pragma unroll
            for (int i = 0; i < 2; i++) {
                uint32_t h0, l0, h1, l1;
                split_pair_rn(pa[i].x, pa[i].y, h0, l0);
                split_pair_rn(pa[i].z, pa[i].w, h1, l1);
                int r = ar + i * 64;
                Ahs[nxt][r][c2] = h0; Ahs[nxt][r][c2 + 1] = h1;
                Als[nxt][r][c2] = l0; Als[nxt][r][c2 + 1] = l1;
            }
            if (vload) {
                const float* e = (const float*)&pv0;
                const float* o = (const float*)&pv1;
                #pragma unroll
                for (int j = 0; j < 4; j++) {
                    uint32_t hh, ll;
                    split_pair_rn(e[j], o[j], hh, ll);
                    Vhs[nxt][vc + j][rp] = hh;
                    Vls[nxt][vc + j][rp] = ll;
                }
            }
            if (kb + 2 < NB) {
                int k0 = (kb + 2) * 16;
                #pragma unroll
                for (int i = 0; i < 2; i++)
                    pa[i] = *(const float4*)&Ab[(size_t)(row0 + ar + i * 64) * N_ + k0 + ac];
                if (vload) {
                    pv0 = *(const float4*)&Vb[(size_t)(k0 + 2 * rp) * DH + vc];
                    pv1 = *(const float4*)&Vb[(size_t)(k0 + 2 * rp + 1) * DH + vc];
                }
            }
        }
        __syncthreads();
    }

    #pragma unroll
    for (int fm = 0; fm < 2; fm++) {
        int n = row0 + wm * 32 + fm * 16 + g;
        #pragma unroll
        for (int fn = 0; fn < 4; fn++) {
            int d = wn * 32 + fn * 8 + 2 * qq;
            float2 p0, p1;
            p0.x = acc[fm][fn][0]; p0.y = acc[fm][fn][1];
            p1.x = acc[fm][fn][2]; p1.y = acc[fm][fn][3];
            *(float2*)&ctx[((size_t)bb * N_ + n) * C_ + h * DH + d] = p0;
            *(float2*)&ctx[((size_t)bb * N_ + n + 8) * C_ + h * DH + d] = p1;
        }
    }
}

// ============ launcher ========================================================
extern "C" void kernel_launch(void* const* d_in, const int* in_sizes, int n_in,
                              void* d_out, int out_size)
{
    const float* x  = (const float*)d_in[0];
    const float* Wq = (const float*)d_in[1];
    const float* bq = (const float*)d_in[2];
    const float* Wk = (const float*)d_in[3];
    const float* bk = (const float*)d_in[4];
    const float* Wv = (const float*)d_in[5];
    const float* bv = (const float*)d_in[6];
    const float* Wo = (const float*)d_in[7];
    const float* bo = (const float*)d_in[8];

    float* out = (float*)d_out;
    const size_t attn_elems = (size_t)B_ * H_ * N_ * N_;
    float* attn = out + ((size_t)out_size - attn_elems);

    float *q, *k, *v, *ctx;
    cudaGetSymbolAddress((void**)&q,   g_q);
    cudaGetSymbolAddress((void**)&k,   g_k);
    cudaGetSymbolAddress((void**)&v,   g_v);
    cudaGetSymbolAddress((void**)&ctx, g_ctx);

    dim3 blk(256);

    qkv_kernel<<<dim3(8, 32, 3), blk>>>(x, Wq, bq, Wk, bk, Wv, bv, q, k, v);
    scores_kernel<<<dim3(8, 8, BH), blk>>>(q, k, attn);
    entmax_kernel<<<dim3(ROWS / 8), blk>>>(attn);
    attnv_kernel<<<dim3(1, 8, BH), blk>>>(attn, v, ctx);
    proj_kernel<<<dim3(8, 32), blk>>>(ctx, Wo, bo, out);
}